// round 15
// baseline (speedup 1.0000x reference)
#include <cuda_runtime.h>
#include <cuda_fp16.h>
#include <math.h>

#define T_ 2048
#define H_ 2048
#define NH_ 16
#define NKV_ 4
#define HD_ 128
#define I_ 1024
#define E_ 16
#define TOPK_ 2
#define P_ (T_*TOPK_)
#define QKVW_ 3072

typedef __half fp16;

// ---------------- scratch (device globals; no allocations allowed) ----------------
__device__ float g_resat[T_*H_];

__device__ fp16 g_qkvh[T_*QKVW_];
__device__ fp16 g_xn[T_*H_];
__device__ fp16 g_attn[T_*H_];
__device__ fp16 g_h2n[T_*H_];
__device__ fp16 g_hmid[T_*H_];
__device__ fp16 g_h3n[T_*H_];
__device__ fp16 g_hmm[P_*I_];
__device__ fp16 g_ymh[P_*H_];

__device__ fp16 g_q[NH_*T_*HD_];
__device__ fp16 g_k[NKV_*T_*HD_];
__device__ fp16 g_v[NKV_*T_*HD_];

__device__ fp16 g_wqkvT[QKVW_*H_];
__device__ fp16 g_woT[H_*H_];
__device__ fp16 g_w13T[2*H_*H_];     // gate/up interleaved rows
__device__ fp16 g_w2T[H_*H_];
__device__ fp16 g_ws[E_*2*I_*H_];    // gate/up interleaved rows per expert
__device__ fp16 g_w2s[E_*H_*I_];

__device__ int   g_topi[P_];
__device__ float g_topw[P_];
__device__ float g_wslot[P_];
__device__ int   g_cnt[E_];
__device__ int   g_off[E_];
__device__ int   g_cur[E_];
__device__ int   g_ptok[P_];
__device__ int   g_pslot[P_];

// ---------------- ptx helpers (base compute_103-safe) ----------------
__device__ __forceinline__ unsigned smem_u32(const void* p) {
  unsigned a;
  asm("{ .reg .u64 t; cvta.to.shared.u64 t, %1; cvt.u32.u64 %0, t; }" : "=r"(a) : "l"(p));
  return a;
}
__device__ __forceinline__ void cp16(unsigned dst, const void* src, bool valid) {
  int sz = valid ? 16 : 0;
  asm volatile("cp.async.cg.shared.global [%0], [%1], 16, %2;"
               :: "r"(dst), "l"(src), "r"(sz) : "memory");
}
#define CP_COMMIT() asm volatile("cp.async.commit_group;" ::: "memory")
#define CP_WAIT(n)  asm volatile("cp.async.wait_group %0;" :: "n"(n) : "memory")

__device__ __forceinline__ void ldsm4(unsigned* r, unsigned addr) {
  asm volatile("ldmatrix.sync.aligned.m8n8.x4.shared.b16 {%0,%1,%2,%3}, [%4];"
               : "=r"(r[0]), "=r"(r[1]), "=r"(r[2]), "=r"(r[3]) : "r"(addr));
}
__device__ __forceinline__ void ldsm4t(unsigned* r, unsigned addr) {
  asm volatile("ldmatrix.sync.aligned.m8n8.x4.trans.shared.b16 {%0,%1,%2,%3}, [%4];"
               : "=r"(r[0]), "=r"(r[1]), "=r"(r[2]), "=r"(r[3]) : "r"(addr));
}
__device__ __forceinline__ void mma16816(float* d, const unsigned* a, unsigned b0, unsigned b1) {
  asm volatile("mma.sync.aligned.m16n8k16.row.col.f32.f16.f16.f32 "
               "{%0,%1,%2,%3}, {%4,%5,%6,%7}, {%8,%9}, {%0,%1,%2,%3};"
               : "+f"(d[0]), "+f"(d[1]), "+f"(d[2]), "+f"(d[3])
               : "r"(a[0]), "r"(a[1]), "r"(a[2]), "r"(a[3]), "r"(b0), "r"(b1));
}

// fast 2^y on the FMA pipe (y in [-1e30, 0]); rel err < 3e-6
__device__ __forceinline__ float fexp2(float y) {
  y = fmaxf(y, -120.f);
  float z = y + 12582912.0f;
  int   n = __float_as_int(z) - 0x4B400000;
  float f = y - (z - 12582912.0f);
  float p = 0.0013333558f;
  p = fmaf(p, f, 0.0096181291f);
  p = fmaf(p, f, 0.0555041087f);
  p = fmaf(p, f, 0.2402265069f);
  p = fmaf(p, f, 0.6931471806f);
  p = fmaf(p, f, 1.0f);
  return p * __int_as_float((n + 127) << 23);
}

__device__ __forceinline__ unsigned pack_h2(float a, float b) {
  __half2 t = __floats2half2_rn(a, b);
  return *(unsigned*)&t;
}
__device__ __forceinline__ void store_h4(float4 v, fp16* p) {
  fp16 h[4] = {__float2half_rn(v.x), __float2half_rn(v.y), __float2half_rn(v.z), __float2half_rn(v.w)};
  *(uint2*)p = *(uint2*)h;
}
__device__ __forceinline__ float siluf(float g){ return g / (1.f + __expf(-g)); }

// ---------------- weight prep ----------------
__global__ void __launch_bounds__(256) convert_ws_int(const float* __restrict__ in, fp16* __restrict__ o) {
  size_t idx = (size_t)blockIdx.x * 256 + threadIdx.x;
  size_t r = idx >> 8;
  int h0 = (int)(idx & 255) << 3;
  int e = (int)(r >> 11);
  int k = (int)(r & 2047);
  int srcr = e * 2 * I_ + ((k & 1) ? I_ + (k >> 1) : (k >> 1));
  const float4* s = (const float4*)(in + (size_t)srcr * H_ + h0);
  float4 a = s[0], b = s[1];
  fp16 hb[8] = {__float2half_rn(a.x), __float2half_rn(a.y), __float2half_rn(a.z), __float2half_rn(a.w),
                __float2half_rn(b.x), __float2half_rn(b.y), __float2half_rn(b.z), __float2half_rn(b.w)};
  *(uint4*)(o + r * H_ + h0) = *(uint4*)hb;
}

__global__ void __launch_bounds__(256) convert_h8(const float* __restrict__ in, fp16* __restrict__ o) {
  size_t i = ((size_t)blockIdx.x * 256 + threadIdx.x) << 3;
  const float4* s = (const float4*)(in + i);
  float4 a = s[0], b = s[1];
  fp16 hb[8] = {__float2half_rn(a.x), __float2half_rn(a.y), __float2half_rn(a.z), __float2half_rn(a.w),
                __float2half_rn(b.x), __float2half_rn(b.y), __float2half_rn(b.z), __float2half_rn(b.w)};
  *(uint4*)(o + i) = *(uint4*)hb;
}

// transpose: in[K][N] fp32 -> o [N][K] fp16; il=1 interleaves gate/up dest rows.
__global__ void __launch_bounds__(256) transpose_h(const float* __restrict__ in, fp16* __restrict__ o,
                                                   int K, int N, int il) {
  __shared__ float t[32][33];
  int k0 = blockIdx.y * 32, n0 = blockIdx.x * 32;
  int tx = threadIdx.x & 31, ty = threadIdx.x >> 5;
  #pragma unroll
  for (int j = 0; j < 4; j++)
    t[ty + 8 * j][tx] = in[(size_t)(k0 + ty + 8 * j) * N + n0 + tx];
  __syncthreads();
  int half = N >> 1;
  #pragma unroll
  for (int j = 0; j < 4; j++) {
    int n = n0 + ty + 8 * j;
    int dr = il ? ((n < half) ? 2 * n : 2 * (n - half) + 1) : n;
    o[(size_t)dr * K + k0 + tx] = __float2half_rn(t[tx][ty + 8 * j]);
  }
}

// ---------------- RMSNorm (single + dual output) ----------------
__global__ void __launch_bounds__(256) rmsnorm_h(const float* __restrict__ x,
                                                 const float* __restrict__ w,
                                                 fp16* __restrict__ o) {
  const int t = blockIdx.x;
  const float4* xr = (const float4*)(x + (size_t)t * H_);
  const float4* wr = (const float4*)w;
  const int i0 = threadIdx.x, i1 = threadIdx.x + 256;
  float4 v0 = xr[i0], v1 = xr[i1];
  float s = v0.x*v0.x+v0.y*v0.y+v0.z*v0.z+v0.w*v0.w
          + v1.x*v1.x+v1.y*v1.y+v1.z*v1.z+v1.w*v1.w;
  #pragma unroll
  for (int off = 16; off; off >>= 1) s += __shfl_xor_sync(0xffffffffu, s, off);
  __shared__ float red[8];
  __shared__ float sinv;
  if ((threadIdx.x & 31) == 0) red[threadIdx.x >> 5] = s;
  __syncthreads();
  if (threadIdx.x == 0) {
    float tt = 0.f;
    #pragma unroll
    for (int k = 0; k < 8; k++) tt += red[k];
    sinv = rsqrtf(tt * (1.f / H_) + 1e-5f);
  }
  __syncthreads();
  float r = sinv;
  float4 w0 = wr[i0], w1 = wr[i1];
  float4 o0, o1;
  o0.x=v0.x*r*w0.x; o0.y=v0.y*r*w0.y; o0.z=v0.z*r*w0.z; o0.w=v0.w*r*w0.w;
  o1.x=v1.x*r*w1.x; o1.y=v1.y*r*w1.y; o1.z=v1.z*r*w1.z; o1.w=v1.w*r*w1.w;
  size_t base = (size_t)t * H_;
  store_h4(o0, o + base + i0 * 4);
  store_h4(o1, o + base + i1 * 4);
}

// shared 1/rms reduction, two weight vectors, two outputs (ln_in / ln_post of same x)
__global__ void __launch_bounds__(256) rmsnorm_dual(const float* __restrict__ x,
                                                    const float* __restrict__ wa,
                                                    const float* __restrict__ wb,
                                                    fp16* __restrict__ oa,
                                                    fp16* __restrict__ ob) {
  const int t = blockIdx.x;
  const float4* xr = (const float4*)(x + (size_t)t * H_);
  const int i0 = threadIdx.x, i1 = threadIdx.x + 256;
  float4 v0 = xr[i0], v1 = xr[i1];
  float s = v0.x*v0.x+v0.y*v0.y+v0.z*v0.z+v0.w*v0.w
          + v1.x*v1.x+v1.y*v1.y+v1.z*v1.z+v1.w*v1.w;
  #pragma unroll
  for (int off = 16; off; off >>= 1) s += __shfl_xor_sync(0xffffffffu, s, off);
  __shared__ float red[8];
  __shared__ float sinv;
  if ((threadIdx.x & 31) == 0) red[threadIdx.x >> 5] = s;
  __syncthreads();
  if (threadIdx.x == 0) {
    float tt = 0.f;
    #pragma unroll
    for (int k = 0; k < 8; k++) tt += red[k];
    sinv = rsqrtf(tt * (1.f / H_) + 1e-5f);
  }
  __syncthreads();
  float r = sinv;
  size_t base = (size_t)t * H_;
  {
    float4 wA0 = ((const float4*)wa)[i0], wA1 = ((const float4*)wa)[i1];
    float4 a0 = make_float4(v0.x*r*wA0.x, v0.y*r*wA0.y, v0.z*r*wA0.z, v0.w*r*wA0.w);
    float4 a1 = make_float4(v1.x*r*wA1.x, v1.y*r*wA1.y, v1.z*r*wA1.z, v1.w*r*wA1.w);
    store_h4(a0, oa + base + i0 * 4);
    store_h4(a1, oa + base + i1 * 4);
  }
  {
    float4 wB0 = ((const float4*)wb)[i0], wB1 = ((const float4*)wb)[i1];
    float4 b0 = make_float4(v0.x*r*wB0.x, v0.y*r*wB0.y, v0.z*r*wB0.z, v0.w*r*wB0.w);
    float4 b1 = make_float4(v1.x*r*wB1.x, v1.y*r*wB1.y, v1.z*r*wB1.z, v1.w*r*wB1.w);
    store_h4(b0, ob + base + i0 * 4);
    store_h4(b1, ob + base + i1 * 4);
  }
}

// ---------------- mma.sync fp16 GEMM with fused epilogues ----------------
// CTA tile 128x128, 8 warps (2m x 4n), warp tile 64x32, K-chunk 64, 2-stage cp.async.
// 2 CTAs/SM. modes:
// 0: fp32 to C.  1: gate/up interleaved -> silu(g)*u fp16 to Ch (Nout=N/2).
// 2: C = Xres + acc (fp32, dense).  3: fp16 to Ch.
// 4: fp16 to Ch scaled by g_wslot[row] (grouped=2 MoE down-proj).
// 5: C = Xres + acc + g_ymh[pslot[2row]] + g_ymh[pslot[2row+1]]  (final, dense).
#define MMA_STG 36864
#define MMA_SMEM (2*MMA_STG + 512)
__global__ void __launch_bounds__(256, 2) mma_gemm(const fp16* __restrict__ A,
                                                   const fp16* __restrict__ B,
                                                   float* __restrict__ C,
                                                   fp16* __restrict__ Ch,
                                                   const float* __restrict__ Xres,
                                                   int N, int K, int grouped, int mode) {
  extern __shared__ char smem[];
  const int tid = threadIdx.x, wid = tid >> 5, lane = tid & 31;
  const int e = blockIdx.z;
  int count = 0, sbase = 0;
  if (grouped) {
    count = g_cnt[e];
    if ((int)(blockIdx.y << 7) >= count) return;
    sbase = g_off[e];
  }
  const fp16* BE = B + (size_t)e * N * K;
  const int m0 = blockIdx.y << 7, n0 = blockIdx.x << 7;
  unsigned sb = smem_u32(smem);
  int* rowmap = (int*)(smem + 2*MMA_STG);

  if (tid < 128) {
    int gr = m0 + tid;
    if (grouped) {
      if (m0 + tid < count) {
        int slot = sbase + m0 + tid;
        gr = (grouped == 1) ? g_ptok[slot] : slot;
      } else gr = -1;
    }
    rowmap[tid] = gr;
  }
  __syncthreads();

  const int nk = K >> 6;
  auto load_chunk = [&](int c, int st) {
    unsigned base = sb + (unsigned)st * MMA_STG;
    #pragma unroll
    for (int i = 0; i < 8; i++) {              // A+B: 2048 cp16
      int s = tid + (i << 8);
      int mat = s >> 10, r = (s >> 3) & 127, cq = s & 7;
      unsigned dst = base + (unsigned)mat * 18432u + (unsigned)(r * 144 + cq * 16);
      const fp16* src;
      bool valid = true;
      if (mat == 0) {
        int gr = rowmap[r];
        valid = (gr >= 0);
        if (!valid) gr = 0;
        src = A + (size_t)gr * K + (c << 6) + (cq << 3);
      } else {
        src = BE + (size_t)(n0 + r) * K + (c << 6) + (cq << 3);
      }
      cp16(dst, src, valid);
    }
    CP_COMMIT();
  };

  float acc[4][4][4];
  #pragma unroll
  for (int i = 0; i < 4; i++)
    #pragma unroll
    for (int j = 0; j < 4; j++)
      #pragma unroll
      for (int k = 0; k < 4; k++) acc[i][j][k] = 0.f;

  const int wm = (wid >> 2) << 6;           // 0 or 64
  const int wn = (wid & 3) << 5;            // 0,32,64,96
  const int ar  = lane & 15;
  const unsigned aco = (lane & 16) ? 16u : 0u;
  const int bn  = (lane & 7) + ((lane & 16) ? 8 : 0);
  const unsigned bko = (lane & 8) ? 16u : 0u;

  load_chunk(0, 0);
  for (int c = 0; c < nk; c++) {
    const int st = c & 1;
    if (c + 1 < nk) { load_chunk(c + 1, st ^ 1); CP_WAIT(1); }
    else CP_WAIT(0);
    __syncthreads();
    const unsigned stb = sb + (unsigned)st * MMA_STG;
    #pragma unroll
    for (int ks = 0; ks < 4; ks++) {
      const unsigned kb = (unsigned)(ks << 5);
      unsigned ahf[4][4];
      #pragma unroll
      for (int mi = 0; mi < 4; mi++) {
        unsigned rowA = (unsigned)((wm + mi * 16 + ar) * 144);
        ldsm4(ahf[mi], stb + rowA + kb + aco);
      }
      #pragma unroll
      for (int nb = 0; nb < 2; nb++) {
        unsigned rowB = (unsigned)((wn + nb * 16 + bn) * 144);
        unsigned bhf[4];
        ldsm4(bhf, stb + 18432u + rowB + kb + bko);
        #pragma unroll
        for (int mi = 0; mi < 4; mi++) {
          #pragma unroll
          for (int half = 0; half < 2; half++) {
            mma16816(acc[mi][nb * 2 + half], ahf[mi], bhf[half * 2], bhf[half * 2 + 1]);
          }
        }
      }
    }
    __syncthreads();
  }

  #pragma unroll
  for (int mi = 0; mi < 4; mi++) {
    const int lr0 = wm + mi * 16 + (lane >> 2);
    const int gr0 = m0 + lr0;
    const bool st0 = !grouped || (gr0 < count);
    const bool st1 = !grouped || (gr0 + 8 < count);
    const size_t row0 = (size_t)((grouped ? sbase : 0) + gr0);
    if (mode == 1) {
      const int Nout = N >> 1;
      #pragma unroll
      for (int nt = 0; nt < 4; nt++) {
        const int col = n0 + wn + nt * 8 + ((lane & 3) << 1);
        const int j = col >> 1;
        float* d = acc[mi][nt];
        if (st0) Ch[row0 * Nout + j]       = __float2half_rn(siluf(d[0]) * d[1]);
        if (st1) Ch[(row0 + 8) * Nout + j] = __float2half_rn(siluf(d[2]) * d[3]);
      }
    } else if (mode == 2) {
      #pragma unroll
      for (int nt = 0; nt < 4; nt++) {
        const int col = n0 + wn + nt * 8 + ((lane & 3) << 1);
        float* d = acc[mi][nt];
        float2 r0 = *(const float2*)(Xres + row0 * N + col);
        float2 r1 = *(const float2*)(Xres + (row0 + 8) * N + col);
        *(float2*)(C + row0 * N + col)       = make_float2(r0.x + d[0], r0.y + d[1]);
        *(float2*)(C + (row0 + 8) * N + col) = make_float2(r1.x + d[2], r1.y + d[3]);
      }
    } else if (mode == 3) {
      #pragma unroll
      for (int nt = 0; nt < 4; nt++) {
        const int col = n0 + wn + nt * 8 + ((lane & 3) << 1);
        float* d = acc[mi][nt];
        if (st0) *(unsigned*)(Ch + row0 * N + col)       = pack_h2(d[0], d[1]);
        if (st1) *(unsigned*)(Ch + (row0 + 8) * N + col) = pack_h2(d[2], d[3]);
      }
    } else if (mode == 4) {
      const float w0s = st0 ? g_wslot[row0]     : 0.f;
      const float w1s = st1 ? g_wslot[row0 + 8] : 0.f;
      #pragma unroll
      for (int nt = 0; nt < 4; nt++) {
        const int col = n0 + wn + nt * 8 + ((lane & 3) << 1);
        float* d = acc[mi][nt];
        if (st0) *(unsigned*)(Ch + row0 * N + col)       = pack_h2(d[0] * w0s, d[1] * w0s);
        if (st1) *(unsigned*)(Ch + (row0 + 8) * N + col) = pack_h2(d[2] * w1s, d[3] * w1s);
      }
    } else if (mode == 5) {
      const int pa0 = g_pslot[2 * (int)row0],       pa1 = g_pslot[2 * (int)row0 + 1];
      const int pb0 = g_pslot[2 * ((int)row0 + 8)], pb1 = g_pslot[2 * ((int)row0 + 8) + 1];
      #pragma unroll
      for (int nt = 0; nt < 4; nt++) {
        const int col = n0 + wn + nt * 8 + ((lane & 3) << 1);
        float* d = acc[mi][nt];
        float2 r0 = *(const float2*)(Xres + row0 * N + col);
        float2 r1 = *(const float2*)(Xres + (row0 + 8) * N + col);
        float2 ya0 = __half22float2(*(const __half2*)(g_ymh + (size_t)pa0 * N + col));
        float2 ya1 = __half22float2(*(const __half2*)(g_ymh + (size_t)pa1 * N + col));
        float2 yb0 = __half22float2(*(const __half2*)(g_ymh + (size_t)pb0 * N + col));
        float2 yb1 = __half22float2(*(const __half2*)(g_ymh + (size_t)pb1 * N + col));
        *(float2*)(C + row0 * N + col) =
            make_float2(r0.x + d[0] + ya0.x + ya1.x, r0.y + d[1] + ya0.y + ya1.y);
        *(float2*)(C + (row0 + 8) * N + col) =
            make_float2(r1.x + d[2] + yb0.x + yb1.x, r1.y + d[3] + yb0.y + yb1.y);
      }
    } else {
      #pragma unroll
      for (int nt = 0; nt < 4; nt++) {
        const int col = n0 + wn + nt * 8 + ((lane & 3) << 1);
        float* d = acc[mi][nt];
        if (st0) *(float2*)(C + row0 * N + col)       = make_float2(d[0], d[1]);
        if (st1) *(float2*)(C + (row0 + 8) * N + col) = make_float2(d[2], d[3]);
      }
    }
  }
}

// ---------------- RoPE + pack into per-head fp16 layouts (fp16 input) ----------------
__global__ void rope_split_kernel(const fp16* __restrict__ qkv) {
  const int t = blockIdx.x, hh = blockIdx.y, i = threadIdx.x;
  if (hh < NH_ + NKV_) {
    const fp16* b;
    fp16* d;
    if (hh < NH_) {
      b = qkv + (size_t)t*QKVW_ + hh*HD_;
      d = g_q + ((size_t)hh*T_ + t) * HD_;
    } else {
      int k = hh - NH_;
      b = qkv + (size_t)t*QKVW_ + NH_*HD_ + k*HD_;
      d = g_k + ((size_t)k*T_ + t) * HD_;
    }
    float fr = powf(10000.f, -(float)(2*i) * (1.f/HD_));
    float ang = (float)t * fr;
    float sn, cs; sincosf(ang, &sn, &cs);
    float x1 = __half2float(b[i]), x2 = __half2float(b[i+64]);
    d[i]      = __float2half_rn(x1*cs - x2*sn);
    d[i + 64] = __float2half_rn(x2*cs + x1*sn);
  } else {
    int v = hh - NH_ - NKV_;
    const fp16* b = qkv + (size_t)t*QKVW_ + (NH_+NKV_)*HD_ + v*HD_;
    size_t o = ((size_t)v*T_ + t) * HD_;
    g_v[o + i]      = b[i];
    g_v[o + i + 64] = b[i+64];
  }
}

// ---------------- mma.sync flash attention (single fp16) ----------------
#define AT_RS  272
#define AT_QSZ (128*AT_RS)
#define AT_TSZ (64*AT_RS)
#define AT_SMEM (AT_QSZ + 2*2*AT_TSZ)   // 104448
__global__ void __launch_bounds__(256) attn_mma(fp16* __restrict__ out) {
  extern __shared__ char smc[];
  const int h = blockIdx.x;
  const int q0 = ((int)gridDim.y - 1 - (int)blockIdx.y) << 7;   // heavy tiles first
  const int kvh = h >> 2;
  const int tid = threadIdx.x, wid = tid >> 5, lane = tid & 31;
  const unsigned sb = smem_u32(smc);
  const unsigned KV_o = AT_QSZ;

  #pragma unroll
  for (int i = 0; i < 8; i++) {
    int s = tid + (i << 8);
    int r = (s >> 4) & 127, cq = s & 15;
    unsigned dst = sb + (unsigned)(r * AT_RS + cq * 16);
    const fp16* src = g_q + (((size_t)h*T_ + q0 + r) << 7) + cq*8;
    cp16(dst, src, true);
  }
  CP_COMMIT();

  auto load_kv = [&](int c, int st) {
    unsigned base = sb + KV_o + (unsigned)st * (2*AT_TSZ);
    #pragma unroll
    for (int i = 0; i < 8; i++) {
      int s = tid + (i << 8);
      int mat = s >> 10, r = (s >> 4) & 63, cq = s & 15;
      unsigned dst = base + (unsigned)mat * AT_TSZ + (unsigned)(r * AT_RS + cq * 16);
      const fp16* ap = (mat == 0) ? g_k : g_v;
      cp16(dst, ap + (((size_t)kvh*T_ + c*64 + r) << 7) + cq*8, true);
    }
    CP_COMMIT();
  };

  const int wr0 = wid << 4;
  const int rlo = q0 + wr0 + (lane >> 2);
  float m0 = -1e30f, m1 = -1e30f, l0 = 0.f, l1 = 0.f;
  float o[16][4];
  #pragma unroll
  for (int i = 0; i < 16; i++)
    #pragma unroll
    for (int j = 0; j < 4; j++) o[i][j] = 0.f;

  const int ntl = (q0 >> 6) + 2;
  load_kv(0, 0);

  const int ar  = lane & 15;
  const int aco = (lane >> 4) << 4;
  const int bnr = (lane & 7) + ((lane & 16) ? 8 : 0);
  const int bko = (lane & 8) ? 16 : 0;
  const float sc = 0.12751744f;                    // (1/sqrt(128)) * log2(e)

  for (int c = 0; c < ntl; c++) {
    const int st = c & 1;
    if (c + 1 < ntl) { load_kv(c + 1, st ^ 1); CP_WAIT(1); }
    else CP_WAIT(0);
    __syncthreads();
    const int s0 = c << 6;
    const bool active = (s0 <= q0 + wr0 + 15);
    if (active) {
      const unsigned kvb = sb + KV_o + (unsigned)st * (2*AT_TSZ);
      float s8[8][4];
      #pragma unroll
      for (int i = 0; i < 8; i++)
        #pragma unroll
        for (int j = 0; j < 4; j++) s8[i][j] = 0.f;
      #pragma unroll
      for (int kk = 0; kk < 8; kk++) {
        const unsigned qoff = (unsigned)((wr0 + ar) * AT_RS + kk * 32 + aco);
        unsigned ah[4];
        ldsm4(ah, sb + qoff);
        #pragma unroll
        for (int ntp = 0; ntp < 4; ntp++) {
          const unsigned koff = (unsigned)((bnr + ntp * 16) * AT_RS + kk * 32 + bko);
          unsigned bh[4];
          ldsm4(bh, kvb + koff);
          #pragma unroll
          for (int hf = 0; hf < 2; hf++)
            mma16816(s8[ntp * 2 + hf], ah, bh[hf*2], bh[hf*2+1]);
        }
      }
      #pragma unroll
      for (int nt = 0; nt < 8; nt++)
        #pragma unroll
        for (int j = 0; j < 4; j++) s8[nt][j] *= sc;
      if (s0 + 63 > q0 + wr0) {
        const int cb = s0 + ((lane & 3) << 1);
        #pragma unroll
        for (int nt = 0; nt < 8; nt++) {
          #pragma unroll
          for (int j = 0; j < 2; j++) {
            int col = cb + nt * 8 + j;
            if (col > rlo)     s8[nt][j]     = -1e30f;
            if (col > rlo + 8) s8[nt][j + 2] = -1e30f;
          }
        }
      }
      float tm0 = -1e30f, tm1 = -1e30f;
      #pragma unroll
      for (int nt = 0; nt < 8; nt++) {
        tm0 = fmaxf(tm0, fmaxf(s8[nt][0], s8[nt][1]));
        tm1 = fmaxf(tm1, fmaxf(s8[nt][2], s8[nt][3]));
      }
      tm0 = fmaxf(tm0, __shfl_xor_sync(0xffffffffu, tm0, 1));
      tm0 = fmaxf(tm0, __shfl_xor_sync(0xffffffffu, tm0, 2));
      tm1 = fmaxf(tm1, __shfl_xor_sync(0xffffffffu, tm1, 1));
      tm1 = fmaxf(tm1, __shfl_xor_sync(0xffffffffu, tm1, 2));
      const float mn0 = fmaxf(m0, tm0), mn1 = fmaxf(m1, tm1);
      const float aa0 = fexp2(m0 - mn0), aa1 = fexp2(m1 - mn1);
      m0 = mn0; m1 = mn1;
      float ts0 = 0.f, ts1 = 0.f;
      unsigned pH[4][4];
      #pragma unroll
      for (int kc = 0; kc < 4; kc++) {
        float e00 = fexp2(s8[2*kc][0]   - m0), e01 = fexp2(s8[2*kc][1]   - m0);
        float e02 = fexp2(s8[2*kc][2]   - m1), e03 = fexp2(s8[2*kc][3]   - m1);
        float e10 = fexp2(s8[2*kc+1][0] - m0), e11 = fexp2(s8[2*kc+1][1] - m0);
        float e12 = fexp2(s8[2*kc+1][2] - m1), e13 = fexp2(s8[2*kc+1][3] - m1);
        ts0 += e00 + e01 + e10 + e11;
        ts1 += e02 + e03 + e12 + e13;
        pH[kc][0] = pack_h2(e00, e01);
        pH[kc][1] = pack_h2(e02, e03);
        pH[kc][2] = pack_h2(e10, e11);
        pH[kc][3] = pack_h2(e12, e13);
      }
      ts0 += __shfl_xor_sync(0xffffffffu, ts0, 1);
      ts0 += __shfl_xor_sync(0xffffffffu, ts0, 2);
      ts1 += __shfl_xor_sync(0xffffffffu, ts1, 1);
      ts1 += __shfl_xor_sync(0xffffffffu, ts1, 2);
      l0 = l0 * aa0 + ts0;
      l1 = l1 * aa1 + ts1;
      #pragma unroll
      for (int nt = 0; nt < 16; nt++) {
        o[nt][0] *= aa0; o[nt][1] *= aa0;
        o[nt][2] *= aa1; o[nt][3] *= aa1;
      }
      #pragma unroll
      for (int kc = 0; kc < 4; kc++) {
        #pragma unroll
        for (int ntp = 0; ntp < 8; ntp++) {
          const unsigned voff = (unsigned)((kc * 16 + ar) * AT_RS + ntp * 32 + aco);
          unsigned vh[4];
          ldsm4t(vh, kvb + AT_TSZ + voff);
          #pragma unroll
          for (int hf = 0; hf < 2; hf++)
            mma16816(o[ntp * 2 + hf], pH[kc], vh[hf*2], vh[hf*2+1]);
        }
      }
    }
    __syncthreads();
  }

  const float inv0 = 1.f / l0, inv1 = 1.f / l1;
  #pragma unroll
  for (int nt = 0; nt < 16; nt++) {
    const int col = h * HD_ + nt * 8 + ((lane & 3) << 1);
    size_t b0 = (size_t)rlo * H_ + col;
    size_t b1 = (size_t)(rlo + 8) * H_ + col;
    *(unsigned*)(out + b0) = pack_h2(o[nt][0] * inv0, o[nt][1] * inv0);
    *(unsigned*)(out + b1) = pack_h2(o[nt][2] * inv1, o[nt][3] * inv1);
  }
}

// ---------------- gating + routing ----------------
__global__ void __launch_bounds__(256) gate_kernel(const float* __restrict__ gw) {
  const int t = blockIdx.x;
  __shared__ float part[256];
  const int tid = threadIdx.x;
  const int e = tid & 15, c = tid >> 4;
  const fp16* xh = g_h3n + (size_t)t*H_;
  float s = 0.f;
  for (int h = c*128; h < c*128+128; h++)
    s += __half2float(xh[h]) * gw[h*E_ + e];
  part[tid] = s;
  __syncthreads();
  if (tid == 0) {
    float lg[16];
    for (int ee=0; ee<16; ee++){ float v=0.f; for (int cc=0; cc<16; cc++) v += part[cc*16+ee]; lg[ee]=v; }
    int i1 = 0;
    for (int ee=1; ee<16; ee++) if (lg[ee] > lg[i1]) i1 = ee;
    int i2 = (i1==0) ? 1 : 0;
    for (int ee=0; ee<16; ee++) if (ee!=i1 && lg[ee] > lg[i2]) i2 = ee;
    float mx = lg[i1];
    float p1 = expf(lg[i1]-mx), p2 = expf(lg[i2]-mx);
    float d = p1 + p2;
    g_topi[t*2]=i1; g_topi[t*2+1]=i2;
    g_topw[t*2]=p1/d; g_topw[t*2+1]=p2/d;
  }
}

__global__ void moe_zero_kernel(){ if (threadIdx.x < E_){ g_cnt[threadIdx.x]=0; g_cur[threadIdx.x]=0; } }
__global__ void moe_count_kernel(){ int i = blockIdx.x*256+threadIdx.x; if (i < P_) atomicAdd(&g_cnt[g_topi[i]], 1); }
__global__ void moe_scan_kernel(){ if (threadIdx.x==0){ int o=0; for (int e=0;e<E_;e++){ g_off[e]=o; o+=g_cnt[e]; } } }
__global__ void moe_scatter_kernel(){
  int i = blockIdx.x*256+threadIdx.x;
  if (i < P_) {
    int e = g_topi[i];
    int pos = g_off[e] + atomicAdd(&g_cur[e], 1);
    g_ptok[pos] = i >> 1;
    g_pslot[i]  = pos;
    g_wslot[pos] = g_topw[i];
  }
}

// ---------------- host ----------------
extern "C" void kernel_launch(void* const* d_in, const int* in_sizes, int n_in,
                              void* d_out, int out_size) {
  (void)in_sizes; (void)n_in; (void)out_size;
  const float* x      = (const float*)d_in[0];
  const float* ln_in  = (const float*)d_in[1];
  const float* ln_post= (const float*)d_in[2];
  const float* ln_res = (const float*)d_in[3];
  const float* wqkv   = (const float*)d_in[4];
  const float* wo     = (const float*)d_in[5];
  const float* w13    = (const float*)d_in[6];
  const float* w2     = (const float*)d_in[7];
  const float* gw     = (const float*)d_in[8];
  const float* ws     = (const float*)d_in[9];
  const float* w2s    = (const float*)d_in[10];
  float* out = (float*)d_out;

  float *resat;
  cudaGetSymbolAddress((void**)&resat,g_resat);

  fp16 *qkvh,*xn,*attn,*h2n,*hmid,*h3n,*hmm,*ymh;
  cudaGetSymbolAddress((void**)&qkvh, g_qkvh);
  cudaGetSymbolAddress((void**)&xn,   g_xn);
  cudaGetSymbolAddress((void**)&attn, g_attn);
  cudaGetSymbolAddress((void**)&h2n,  g_h2n);
  cudaGetSymbolAddress((void**)&hmid, g_hmid);
  cudaGetSymbolAddress((void**)&h3n,  g_h3n);
  cudaGetSymbolAddress((void**)&hmm,  g_hmm);
  cudaGetSymbolAddress((void**)&ymh,  g_ymh);

  fp16 *wq,*wo16,*w1316,*w216,*ws16,*w2s16;
  cudaGetSymbolAddress((void**)&wq,    g_wqkvT);
  cudaGetSymbolAddress((void**)&wo16,  g_woT);
  cudaGetSymbolAddress((void**)&w1316, g_w13T);
  cudaGetSymbolAddress((void**)&w216,  g_w2T);
  cudaGetSymbolAddress((void**)&ws16,  g_ws);
  cudaGetSymbolAddress((void**)&w2s16, g_w2s);

  cudaFuncSetAttribute(mma_gemm, cudaFuncAttributeMaxDynamicSharedMemorySize, MMA_SMEM);
  cudaFuncSetAttribute(attn_mma, cudaFuncAttributeMaxDynamicSharedMemorySize, AT_SMEM);

  // fork a side stream (host objects only; created once per host invocation).
  cudaStream_t s1;
  cudaStreamCreateWithFlags(&s1, cudaStreamNonBlocking);
  cudaEvent_t evFork, evWq, evW, evXN, evJoin;
  cudaEventCreateWithFlags(&evFork, cudaEventDisableTiming);
  cudaEventCreateWithFlags(&evWq,   cudaEventDisableTiming);
  cudaEventCreateWithFlags(&evW,    cudaEventDisableTiming);
  cudaEventCreateWithFlags(&evXN,   cudaEventDisableTiming);
  cudaEventCreateWithFlags(&evJoin, cudaEventDisableTiming);

  cudaEventRecord(evFork, 0);
  cudaStreamWaitEvent(s1, evFork, 0);

  // ---- main stream start: shared-reduction dual rmsnorm (xn for attn, h3n for MoE) ----
  rmsnorm_dual<<<T_, 256>>>(x, ln_in, ln_post, xn, h3n);
  cudaEventRecord(evXN, 0);

  // ---- side stream: wqkv transpose first (main waits on it), then the rest ----
  transpose_h<<<dim3(QKVW_/32, H_/32), 256, 0, s1>>>(wqkv, wq, H_, QKVW_, 0);
  cudaEventRecord(evWq, s1);
  transpose_h<<<dim3(H_/32,   H_/32), 256, 0, s1>>>(wo,  wo16,  H_, H_, 0);
  transpose_h<<<dim3(2*H_/32, H_/32), 256, 0, s1>>>(w13, w1316, H_, 2*H_, 1);
  transpose_h<<<dim3(H_/32,   H_/32), 256, 0, s1>>>(w2,  w216,  H_, H_, 0);
  cudaEventRecord(evW, s1);
  convert_ws_int<<<(E_*2*I_*H_)/2048, 256, 0, s1>>>(ws, ws16);
  convert_h8<<<(E_*H_*I_)/2048, 256, 0, s1>>>(w2s, w2s16);
  cudaStreamWaitEvent(s1, evXN, 0);
  gate_kernel<<<T_, 256, 0, s1>>>(gw);
  moe_zero_kernel<<<1, 32, 0, s1>>>();
  moe_count_kernel<<<P_/256, 256, 0, s1>>>();
  moe_scan_kernel<<<1, 32, 0, s1>>>();
  moe_scatter_kernel<<<P_/256, 256, 0, s1>>>();
  mma_gemm<<<dim3(2*I_/128, T_/128, E_), 256, MMA_SMEM, s1>>>(h3n, ws16, nullptr, hmm, nullptr, 2*I_, H_, 1, 1);
  mma_gemm<<<dim3(H_/128, T_/128, E_), 256, MMA_SMEM, s1>>>(hmm, w2s16, nullptr, ymh, nullptr, H_, I_, 2, 4);
  cudaEventRecord(evJoin, s1);

  // ---- main stream: attention chain + residual MLP (+ fused final) ----
  cudaStreamWaitEvent(0, evWq, 0);
  mma_gemm<<<dim3(QKVW_/128, T_/128, 1), 256, MMA_SMEM>>>(xn, wq, nullptr, qkvh, nullptr, QKVW_, H_, 0, 3);
  rope_split_kernel<<<dim3(T_, NH_ + 2*NKV_), 64>>>(qkvh);
  attn_mma<<<dim3(NH_, T_/128), 256, AT_SMEM>>>(attn);
  cudaStreamWaitEvent(0, evW, 0);
  mma_gemm<<<dim3(H_/128, T_/128, 1), 256, MMA_SMEM>>>(attn, wo16, resat, nullptr, x, H_, H_, 0, 2);
  rmsnorm_h<<<T_, 256>>>(resat, ln_res, h2n);
  mma_gemm<<<dim3(2*H_/128, T_/128, 1), 256, MMA_SMEM>>>(h2n, w1316, nullptr, hmid, nullptr, 2*H_, H_, 0, 1);
  cudaStreamWaitEvent(0, evJoin, 0);
  mma_gemm<<<dim3(H_/128, T_/128, 1), 256, MMA_SMEM>>>(hmid, w216, out, nullptr, resat, H_, H_, 0, 5);
}

// round 16
// speedup vs baseline: 1.0034x; 1.0034x over previous
#include <cuda_runtime.h>
#include <cuda_fp16.h>
#include <math.h>

#define T_ 2048
#define H_ 2048
#define NH_ 16
#define NKV_ 4
#define HD_ 128
#define I_ 1024
#define E_ 16
#define TOPK_ 2
#define P_ (T_*TOPK_)
#define QKVW_ 3072

typedef __half fp16;

// ---------------- scratch (device globals; no allocations allowed) ----------------
__device__ float g_resat[T_*H_];

__device__ fp16 g_qkvh[T_*QKVW_];
__device__ fp16 g_xn[T_*H_];
__device__ fp16 g_attn[T_*H_];
__device__ fp16 g_h2n[T_*H_];
__device__ fp16 g_hmid[T_*H_];
__device__ fp16 g_h3n[T_*H_];
__device__ fp16 g_hmm[P_*I_];
__device__ fp16 g_ymh[P_*H_];

__device__ fp16 g_q[NH_*T_*HD_];
__device__ fp16 g_k[NKV_*T_*HD_];
__device__ fp16 g_v[NKV_*T_*HD_];

__device__ fp16 g_wqkvT[QKVW_*H_];
__device__ fp16 g_woT[H_*H_];
__device__ fp16 g_w13T[2*H_*H_];     // gate/up interleaved rows
__device__ fp16 g_w2T[H_*H_];
__device__ fp16 g_ws[E_*2*I_*H_];    // gate/up interleaved rows per expert
__device__ fp16 g_w2s[E_*H_*I_];

__device__ int   g_topi[P_];
__device__ float g_topw[P_];
__device__ float g_wslot[P_];
__device__ int   g_cnt[E_];
__device__ int   g_off[E_];
__device__ int   g_cur[E_];
__device__ int   g_ptok[P_];
__device__ int   g_pslot[P_];

// ---------------- ptx helpers (base compute_103-safe) ----------------
__device__ __forceinline__ unsigned smem_u32(const void* p) {
  unsigned a;
  asm("{ .reg .u64 t; cvta.to.shared.u64 t, %1; cvt.u32.u64 %0, t; }" : "=r"(a) : "l"(p));
  return a;
}
__device__ __forceinline__ void cp16(unsigned dst, const void* src, bool valid) {
  int sz = valid ? 16 : 0;
  asm volatile("cp.async.cg.shared.global [%0], [%1], 16, %2;"
               :: "r"(dst), "l"(src), "r"(sz) : "memory");
}
#define CP_COMMIT() asm volatile("cp.async.commit_group;" ::: "memory")
#define CP_WAIT(n)  asm volatile("cp.async.wait_group %0;" :: "n"(n) : "memory")

__device__ __forceinline__ void ldsm4(unsigned* r, unsigned addr) {
  asm volatile("ldmatrix.sync.aligned.m8n8.x4.shared.b16 {%0,%1,%2,%3}, [%4];"
               : "=r"(r[0]), "=r"(r[1]), "=r"(r[2]), "=r"(r[3]) : "r"(addr));
}
__device__ __forceinline__ void ldsm4t(unsigned* r, unsigned addr) {
  asm volatile("ldmatrix.sync.aligned.m8n8.x4.trans.shared.b16 {%0,%1,%2,%3}, [%4];"
               : "=r"(r[0]), "=r"(r[1]), "=r"(r[2]), "=r"(r[3]) : "r"(addr));
}
__device__ __forceinline__ void mma16816(float* d, const unsigned* a, unsigned b0, unsigned b1) {
  asm volatile("mma.sync.aligned.m16n8k16.row.col.f32.f16.f16.f32 "
               "{%0,%1,%2,%3}, {%4,%5,%6,%7}, {%8,%9}, {%0,%1,%2,%3};"
               : "+f"(d[0]), "+f"(d[1]), "+f"(d[2]), "+f"(d[3])
               : "r"(a[0]), "r"(a[1]), "r"(a[2]), "r"(a[3]), "r"(b0), "r"(b1));
}

// fast 2^y on the FMA pipe (y in [-1e30, 0]); rel err < 3e-6
__device__ __forceinline__ float fexp2(float y) {
  y = fmaxf(y, -120.f);
  float z = y + 12582912.0f;
  int   n = __float_as_int(z) - 0x4B400000;
  float f = y - (z - 12582912.0f);
  float p = 0.0013333558f;
  p = fmaf(p, f, 0.0096181291f);
  p = fmaf(p, f, 0.0555041087f);
  p = fmaf(p, f, 0.2402265069f);
  p = fmaf(p, f, 0.6931471806f);
  p = fmaf(p, f, 1.0f);
  return p * __int_as_float((n + 127) << 23);
}

__device__ __forceinline__ unsigned pack_h2(float a, float b) {
  __half2 t = __floats2half2_rn(a, b);
  return *(unsigned*)&t;
}
__device__ __forceinline__ void store_h4(float4 v, fp16* p) {
  fp16 h[4] = {__float2half_rn(v.x), __float2half_rn(v.y), __float2half_rn(v.z), __float2half_rn(v.w)};
  *(uint2*)p = *(uint2*)h;
}
__device__ __forceinline__ float siluf(float g){ return g / (1.f + __expf(-g)); }

// ---------------- weight prep ----------------
__global__ void __launch_bounds__(256) convert_ws_int(const float* __restrict__ in, fp16* __restrict__ o) {
  size_t idx = (size_t)blockIdx.x * 256 + threadIdx.x;
  size_t r = idx >> 8;
  int h0 = (int)(idx & 255) << 3;
  int e = (int)(r >> 11);
  int k = (int)(r & 2047);
  int srcr = e * 2 * I_ + ((k & 1) ? I_ + (k >> 1) : (k >> 1));
  const float4* s = (const float4*)(in + (size_t)srcr * H_ + h0);
  float4 a = s[0], b = s[1];
  fp16 hb[8] = {__float2half_rn(a.x), __float2half_rn(a.y), __float2half_rn(a.z), __float2half_rn(a.w),
                __float2half_rn(b.x), __float2half_rn(b.y), __float2half_rn(b.z), __float2half_rn(b.w)};
  *(uint4*)(o + r * H_ + h0) = *(uint4*)hb;
}

__global__ void __launch_bounds__(256) convert_h8(const float* __restrict__ in, fp16* __restrict__ o) {
  size_t i = ((size_t)blockIdx.x * 256 + threadIdx.x) << 3;
  const float4* s = (const float4*)(in + i);
  float4 a = s[0], b = s[1];
  fp16 hb[8] = {__float2half_rn(a.x), __float2half_rn(a.y), __float2half_rn(a.z), __float2half_rn(a.w),
                __float2half_rn(b.x), __float2half_rn(b.y), __float2half_rn(b.z), __float2half_rn(b.w)};
  *(uint4*)(o + i) = *(uint4*)hb;
}

// transpose: in[K][N] fp32 -> o [N][K] fp16; il=1 interleaves gate/up dest rows.
__global__ void __launch_bounds__(256) transpose_h(const float* __restrict__ in, fp16* __restrict__ o,
                                                   int K, int N, int il) {
  __shared__ float t[32][33];
  int k0 = blockIdx.y * 32, n0 = blockIdx.x * 32;
  int tx = threadIdx.x & 31, ty = threadIdx.x >> 5;
  #pragma unroll
  for (int j = 0; j < 4; j++)
    t[ty + 8 * j][tx] = in[(size_t)(k0 + ty + 8 * j) * N + n0 + tx];
  __syncthreads();
  int half = N >> 1;
  #pragma unroll
  for (int j = 0; j < 4; j++) {
    int n = n0 + ty + 8 * j;
    int dr = il ? ((n < half) ? 2 * n : 2 * (n - half) + 1) : n;
    o[(size_t)dr * K + k0 + tx] = __float2half_rn(t[tx][ty + 8 * j]);
  }
}

// ---------------- RMSNorm (single + dual output) ----------------
__global__ void __launch_bounds__(256) rmsnorm_h(const float* __restrict__ x,
                                                 const float* __restrict__ w,
                                                 fp16* __restrict__ o) {
  const int t = blockIdx.x;
  const float4* xr = (const float4*)(x + (size_t)t * H_);
  const float4* wr = (const float4*)w;
  const int i0 = threadIdx.x, i1 = threadIdx.x + 256;
  float4 v0 = xr[i0], v1 = xr[i1];
  float s = v0.x*v0.x+v0.y*v0.y+v0.z*v0.z+v0.w*v0.w
          + v1.x*v1.x+v1.y*v1.y+v1.z*v1.z+v1.w*v1.w;
  #pragma unroll
  for (int off = 16; off; off >>= 1) s += __shfl_xor_sync(0xffffffffu, s, off);
  __shared__ float red[8];
  __shared__ float sinv;
  if ((threadIdx.x & 31) == 0) red[threadIdx.x >> 5] = s;
  __syncthreads();
  if (threadIdx.x == 0) {
    float tt = 0.f;
    #pragma unroll
    for (int k = 0; k < 8; k++) tt += red[k];
    sinv = rsqrtf(tt * (1.f / H_) + 1e-5f);
  }
  __syncthreads();
  float r = sinv;
  float4 w0 = wr[i0], w1 = wr[i1];
  float4 o0, o1;
  o0.x=v0.x*r*w0.x; o0.y=v0.y*r*w0.y; o0.z=v0.z*r*w0.z; o0.w=v0.w*r*w0.w;
  o1.x=v1.x*r*w1.x; o1.y=v1.y*r*w1.y; o1.z=v1.z*r*w1.z; o1.w=v1.w*r*w1.w;
  size_t base = (size_t)t * H_;
  store_h4(o0, o + base + i0 * 4);
  store_h4(o1, o + base + i1 * 4);
}

// shared 1/rms reduction, two weight vectors, two outputs (ln_in / ln_post of same x)
__global__ void __launch_bounds__(256) rmsnorm_dual(const float* __restrict__ x,
                                                    const float* __restrict__ wa,
                                                    const float* __restrict__ wb,
                                                    fp16* __restrict__ oa,
                                                    fp16* __restrict__ ob) {
  const int t = blockIdx.x;
  const float4* xr = (const float4*)(x + (size_t)t * H_);
  const int i0 = threadIdx.x, i1 = threadIdx.x + 256;
  float4 v0 = xr[i0], v1 = xr[i1];
  float s = v0.x*v0.x+v0.y*v0.y+v0.z*v0.z+v0.w*v0.w
          + v1.x*v1.x+v1.y*v1.y+v1.z*v1.z+v1.w*v1.w;
  #pragma unroll
  for (int off = 16; off; off >>= 1) s += __shfl_xor_sync(0xffffffffu, s, off);
  __shared__ float red[8];
  __shared__ float sinv;
  if ((threadIdx.x & 31) == 0) red[threadIdx.x >> 5] = s;
  __syncthreads();
  if (threadIdx.x == 0) {
    float tt = 0.f;
    #pragma unroll
    for (int k = 0; k < 8; k++) tt += red[k];
    sinv = rsqrtf(tt * (1.f / H_) + 1e-5f);
  }
  __syncthreads();
  float r = sinv;
  size_t base = (size_t)t * H_;
  {
    float4 wA0 = ((const float4*)wa)[i0], wA1 = ((const float4*)wa)[i1];
    float4 a0 = make_float4(v0.x*r*wA0.x, v0.y*r*wA0.y, v0.z*r*wA0.z, v0.w*r*wA0.w);
    float4 a1 = make_float4(v1.x*r*wA1.x, v1.y*r*wA1.y, v1.z*r*wA1.z, v1.w*r*wA1.w);
    store_h4(a0, oa + base + i0 * 4);
    store_h4(a1, oa + base + i1 * 4);
  }
  {
    float4 wB0 = ((const float4*)wb)[i0], wB1 = ((const float4*)wb)[i1];
    float4 b0 = make_float4(v0.x*r*wB0.x, v0.y*r*wB0.y, v0.z*r*wB0.z, v0.w*r*wB0.w);
    float4 b1 = make_float4(v1.x*r*wB1.x, v1.y*r*wB1.y, v1.z*r*wB1.z, v1.w*r*wB1.w);
    store_h4(b0, ob + base + i0 * 4);
    store_h4(b1, ob + base + i1 * 4);
  }
}

// ---------------- mma.sync fp16 GEMM with fused epilogues ----------------
// CTA tile 128x128, 8 warps (2m x 4n), warp tile 64x32, K-chunk 64, 3-stage cp.async,
// 2 CTAs/SM, ONE barrier per chunk (3-stage makes the trailing barrier redundant).
// modes:
// 0: fp32 to C.  1: gate/up interleaved -> silu(g)*u fp16 to Ch (Nout=N/2).
// 2: C = Xres + acc (fp32, dense).  3: fp16 to Ch.
// 4: fp16 to Ch scaled by g_wslot[row] (grouped=2 MoE down-proj).
// 5: C = Xres + acc + g_ymh[pslot[2row]] + g_ymh[pslot[2row+1]]  (final, dense).
#define MMA_STG 36864
#define MMA_SMEM (3*MMA_STG + 512)
__global__ void __launch_bounds__(256, 2) mma_gemm(const fp16* __restrict__ A,
                                                   const fp16* __restrict__ B,
                                                   float* __restrict__ C,
                                                   fp16* __restrict__ Ch,
                                                   const float* __restrict__ Xres,
                                                   int N, int K, int grouped, int mode) {
  extern __shared__ char smem[];
  const int tid = threadIdx.x, wid = tid >> 5, lane = tid & 31;
  const int e = blockIdx.z;
  int count = 0, sbase = 0;
  if (grouped) {
    count = g_cnt[e];
    if ((int)(blockIdx.y << 7) >= count) return;
    sbase = g_off[e];
  }
  const fp16* BE = B + (size_t)e * N * K;
  const int m0 = blockIdx.y << 7, n0 = blockIdx.x << 7;
  unsigned sb = smem_u32(smem);
  int* rowmap = (int*)(smem + 3*MMA_STG);

  if (tid < 128) {
    int gr = m0 + tid;
    if (grouped) {
      if (m0 + tid < count) {
        int slot = sbase + m0 + tid;
        gr = (grouped == 1) ? g_ptok[slot] : slot;
      } else gr = -1;
    }
    rowmap[tid] = gr;
  }
  __syncthreads();

  const int nk = K >> 6;
  auto load_chunk = [&](int c, int st) {
    unsigned base = sb + (unsigned)st * MMA_STG;
    #pragma unroll
    for (int i = 0; i < 8; i++) {              // A+B: 2048 cp16
      int s = tid + (i << 8);
      int mat = s >> 10, r = (s >> 3) & 127, cq = s & 7;
      unsigned dst = base + (unsigned)mat * 18432u + (unsigned)(r * 144 + cq * 16);
      const fp16* src;
      bool valid = true;
      if (mat == 0) {
        int gr = rowmap[r];
        valid = (gr >= 0);
        if (!valid) gr = 0;
        src = A + (size_t)gr * K + (c << 6) + (cq << 3);
      } else {
        src = BE + (size_t)(n0 + r) * K + (c << 6) + (cq << 3);
      }
      cp16(dst, src, valid);
    }
    CP_COMMIT();
  };

  float acc[4][4][4];
  #pragma unroll
  for (int i = 0; i < 4; i++)
    #pragma unroll
    for (int j = 0; j < 4; j++)
      #pragma unroll
      for (int k = 0; k < 4; k++) acc[i][j][k] = 0.f;

  const int wm = (wid >> 2) << 6;           // 0 or 64
  const int wn = (wid & 3) << 5;            // 0,32,64,96
  const int ar  = lane & 15;
  const unsigned aco = (lane & 16) ? 16u : 0u;
  const int bn  = (lane & 7) + ((lane & 16) ? 8 : 0);
  const unsigned bko = (lane & 8) ? 16u : 0u;

  load_chunk(0, 0);
  if (nk > 1) load_chunk(1, 1);
  int st = 0;
  for (int c = 0; c < nk; c++) {
    if (c + 1 < nk) CP_WAIT(1); else CP_WAIT(0);
    __syncthreads();
    if (c + 2 < nk) {
      int st2 = st + 2; if (st2 >= 3) st2 -= 3;
      load_chunk(c + 2, st2);
    }
    const unsigned stb = sb + (unsigned)st * MMA_STG;
    #pragma unroll
    for (int ks = 0; ks < 4; ks++) {
      const unsigned kb = (unsigned)(ks << 5);
      unsigned ahf[4][4];
      #pragma unroll
      for (int mi = 0; mi < 4; mi++) {
        unsigned rowA = (unsigned)((wm + mi * 16 + ar) * 144);
        ldsm4(ahf[mi], stb + rowA + kb + aco);
      }
      #pragma unroll
      for (int nb = 0; nb < 2; nb++) {
        unsigned rowB = (unsigned)((wn + nb * 16 + bn) * 144);
        unsigned bhf[4];
        ldsm4(bhf, stb + 18432u + rowB + kb + bko);
        #pragma unroll
        for (int mi = 0; mi < 4; mi++) {
          #pragma unroll
          for (int half = 0; half < 2; half++) {
            mma16816(acc[mi][nb * 2 + half], ahf[mi], bhf[half * 2], bhf[half * 2 + 1]);
          }
        }
      }
    }
    // no trailing barrier: with 3 stages, the next write into this buffer (chunk
    // c+3) is issued in iteration c+1 strictly after its top __syncthreads().
    if (++st == 3) st = 0;
  }

  #pragma unroll
  for (int mi = 0; mi < 4; mi++) {
    const int lr0 = wm + mi * 16 + (lane >> 2);
    const int gr0 = m0 + lr0;
    const bool st0 = !grouped || (gr0 < count);
    const bool st1 = !grouped || (gr0 + 8 < count);
    const size_t row0 = (size_t)((grouped ? sbase : 0) + gr0);
    if (mode == 1) {
      const int Nout = N >> 1;
      #pragma unroll
      for (int nt = 0; nt < 4; nt++) {
        const int col = n0 + wn + nt * 8 + ((lane & 3) << 1);
        const int j = col >> 1;
        float* d = acc[mi][nt];
        if (st0) Ch[row0 * Nout + j]       = __float2half_rn(siluf(d[0]) * d[1]);
        if (st1) Ch[(row0 + 8) * Nout + j] = __float2half_rn(siluf(d[2]) * d[3]);
      }
    } else if (mode == 2) {
      #pragma unroll
      for (int nt = 0; nt < 4; nt++) {
        const int col = n0 + wn + nt * 8 + ((lane & 3) << 1);
        float* d = acc[mi][nt];
        float2 r0 = *(const float2*)(Xres + row0 * N + col);
        float2 r1 = *(const float2*)(Xres + (row0 + 8) * N + col);
        *(float2*)(C + row0 * N + col)       = make_float2(r0.x + d[0], r0.y + d[1]);
        *(float2*)(C + (row0 + 8) * N + col) = make_float2(r1.x + d[2], r1.y + d[3]);
      }
    } else if (mode == 3) {
      #pragma unroll
      for (int nt = 0; nt < 4; nt++) {
        const int col = n0 + wn + nt * 8 + ((lane & 3) << 1);
        float* d = acc[mi][nt];
        if (st0) *(unsigned*)(Ch + row0 * N + col)       = pack_h2(d[0], d[1]);
        if (st1) *(unsigned*)(Ch + (row0 + 8) * N + col) = pack_h2(d[2], d[3]);
      }
    } else if (mode == 4) {
      const float w0s = st0 ? g_wslot[row0]     : 0.f;
      const float w1s = st1 ? g_wslot[row0 + 8] : 0.f;
      #pragma unroll
      for (int nt = 0; nt < 4; nt++) {
        const int col = n0 + wn + nt * 8 + ((lane & 3) << 1);
        float* d = acc[mi][nt];
        if (st0) *(unsigned*)(Ch + row0 * N + col)       = pack_h2(d[0] * w0s, d[1] * w0s);
        if (st1) *(unsigned*)(Ch + (row0 + 8) * N + col) = pack_h2(d[2] * w1s, d[3] * w1s);
      }
    } else if (mode == 5) {
      const int pa0 = g_pslot[2 * (int)row0],       pa1 = g_pslot[2 * (int)row0 + 1];
      const int pb0 = g_pslot[2 * ((int)row0 + 8)], pb1 = g_pslot[2 * ((int)row0 + 8) + 1];
      #pragma unroll
      for (int nt = 0; nt < 4; nt++) {
        const int col = n0 + wn + nt * 8 + ((lane & 3) << 1);
        float* d = acc[mi][nt];
        float2 r0 = *(const float2*)(Xres + row0 * N + col);
        float2 r1 = *(const float2*)(Xres + (row0 + 8) * N + col);
        float2 ya0 = __half22float2(*(const __half2*)(g_ymh + (size_t)pa0 * N + col));
        float2 ya1 = __half22float2(*(const __half2*)(g_ymh + (size_t)pa1 * N + col));
        float2 yb0 = __half22float2(*(const __half2*)(g_ymh + (size_t)pb0 * N + col));
        float2 yb1 = __half22float2(*(const __half2*)(g_ymh + (size_t)pb1 * N + col));
        *(float2*)(C + row0 * N + col) =
            make_float2(r0.x + d[0] + ya0.x + ya1.x, r0.y + d[1] + ya0.y + ya1.y);
        *(float2*)(C + (row0 + 8) * N + col) =
            make_float2(r1.x + d[2] + yb0.x + yb1.x, r1.y + d[3] + yb0.y + yb1.y);
      }
    } else {
      #pragma unroll
      for (int nt = 0; nt < 4; nt++) {
        const int col = n0 + wn + nt * 8 + ((lane & 3) << 1);
        float* d = acc[mi][nt];
        if (st0) *(float2*)(C + row0 * N + col)       = make_float2(d[0], d[1]);
        if (st1) *(float2*)(C + (row0 + 8) * N + col) = make_float2(d[2], d[3]);
      }
    }
  }
}

// ---------------- RoPE + pack into per-head fp16 layouts (fp16 input) ----------------
__global__ void rope_split_kernel(const fp16* __restrict__ qkv) {
  const int t = blockIdx.x, hh = blockIdx.y, i = threadIdx.x;
  if (hh < NH_ + NKV_) {
    const fp16* b;
    fp16* d;
    if (hh < NH_) {
      b = qkv + (size_t)t*QKVW_ + hh*HD_;
      d = g_q + ((size_t)hh*T_ + t) * HD_;
    } else {
      int k = hh - NH_;
      b = qkv + (size_t)t*QKVW_ + NH_*HD_ + k*HD_;
      d = g_k + ((size_t)k*T_ + t) * HD_;
    }
    float fr = powf(10000.f, -(float)(2*i) * (1.f/HD_));
    float ang = (float)t * fr;
    float sn, cs; sincosf(ang, &sn, &cs);
    float x1 = __half2float(b[i]), x2 = __half2float(b[i+64]);
    d[i]      = __float2half_rn(x1*cs - x2*sn);
    d[i + 64] = __float2half_rn(x2*cs + x1*sn);
  } else {
    int v = hh - NH_ - NKV_;
    const fp16* b = qkv + (size_t)t*QKVW_ + (NH_+NKV_)*HD_ + v*HD_;
    size_t o = ((size_t)v*T_ + t) * HD_;
    g_v[o + i]      = b[i];
    g_v[o + i + 64] = b[i+64];
  }
}

// ---------------- mma.sync flash attention (single fp16) ----------------
#define AT_RS  272
#define AT_QSZ (128*AT_RS)
#define AT_TSZ (64*AT_RS)
#define AT_SMEM (AT_QSZ + 2*2*AT_TSZ)   // 104448
__global__ void __launch_bounds__(256) attn_mma(fp16* __restrict__ out) {
  extern __shared__ char smc[];
  const int h = blockIdx.x;
  const int q0 = ((int)gridDim.y - 1 - (int)blockIdx.y) << 7;   // heavy tiles first
  const int kvh = h >> 2;
  const int tid = threadIdx.x, wid = tid >> 5, lane = tid & 31;
  const unsigned sb = smem_u32(smc);
  const unsigned KV_o = AT_QSZ;

  #pragma unroll
  for (int i = 0; i < 8; i++) {
    int s = tid + (i << 8);
    int r = (s >> 4) & 127, cq = s & 15;
    unsigned dst = sb + (unsigned)(r * AT_RS + cq * 16);
    const fp16* src = g_q + (((size_t)h*T_ + q0 + r) << 7) + cq*8;
    cp16(dst, src, true);
  }
  CP_COMMIT();

  auto load_kv = [&](int c, int st) {
    unsigned base = sb + KV_o + (unsigned)st * (2*AT_TSZ);
    #pragma unroll
    for (int i = 0; i < 8; i++) {
      int s = tid + (i << 8);
      int mat = s >> 10, r = (s >> 4) & 63, cq = s & 15;
      unsigned dst = base + (unsigned)mat * AT_TSZ + (unsigned)(r * AT_RS + cq * 16);
      const fp16* ap = (mat == 0) ? g_k : g_v;
      cp16(dst, ap + (((size_t)kvh*T_ + c*64 + r) << 7) + cq*8, true);
    }
    CP_COMMIT();
  };

  const int wr0 = wid << 4;
  const int rlo = q0 + wr0 + (lane >> 2);
  float m0 = -1e30f, m1 = -1e30f, l0 = 0.f, l1 = 0.f;
  float o[16][4];
  #pragma unroll
  for (int i = 0; i < 16; i++)
    #pragma unroll
    for (int j = 0; j < 4; j++) o[i][j] = 0.f;

  const int ntl = (q0 >> 6) + 2;
  load_kv(0, 0);

  const int ar  = lane & 15;
  const int aco = (lane >> 4) << 4;
  const int bnr = (lane & 7) + ((lane & 16) ? 8 : 0);
  const int bko = (lane & 8) ? 16 : 0;
  const float sc = 0.12751744f;                    // (1/sqrt(128)) * log2(e)

  for (int c = 0; c < ntl; c++) {
    const int st = c & 1;
    if (c + 1 < ntl) { load_kv(c + 1, st ^ 1); CP_WAIT(1); }
    else CP_WAIT(0);
    __syncthreads();
    const int s0 = c << 6;
    const bool active = (s0 <= q0 + wr0 + 15);
    if (active) {
      const unsigned kvb = sb + KV_o + (unsigned)st * (2*AT_TSZ);
      float s8[8][4];
      #pragma unroll
      for (int i = 0; i < 8; i++)
        #pragma unroll
        for (int j = 0; j < 4; j++) s8[i][j] = 0.f;
      #pragma unroll
      for (int kk = 0; kk < 8; kk++) {
        const unsigned qoff = (unsigned)((wr0 + ar) * AT_RS + kk * 32 + aco);
        unsigned ah[4];
        ldsm4(ah, sb + qoff);
        #pragma unroll
        for (int ntp = 0; ntp < 4; ntp++) {
          const unsigned koff = (unsigned)((bnr + ntp * 16) * AT_RS + kk * 32 + bko);
          unsigned bh[4];
          ldsm4(bh, kvb + koff);
          #pragma unroll
          for (int hf = 0; hf < 2; hf++)
            mma16816(s8[ntp * 2 + hf], ah, bh[hf*2], bh[hf*2+1]);
        }
      }
      #pragma unroll
      for (int nt = 0; nt < 8; nt++)
        #pragma unroll
        for (int j = 0; j < 4; j++) s8[nt][j] *= sc;
      if (s0 + 63 > q0 + wr0) {
        const int cb = s0 + ((lane & 3) << 1);
        #pragma unroll
        for (int nt = 0; nt < 8; nt++) {
          #pragma unroll
          for (int j = 0; j < 2; j++) {
            int col = cb + nt * 8 + j;
            if (col > rlo)     s8[nt][j]     = -1e30f;
            if (col > rlo + 8) s8[nt][j + 2] = -1e30f;
          }
        }
      }
      float tm0 = -1e30f, tm1 = -1e30f;
      #pragma unroll
      for (int nt = 0; nt < 8; nt++) {
        tm0 = fmaxf(tm0, fmaxf(s8[nt][0], s8[nt][1]));
        tm1 = fmaxf(tm1, fmaxf(s8[nt][2], s8[nt][3]));
      }
      tm0 = fmaxf(tm0, __shfl_xor_sync(0xffffffffu, tm0, 1));
      tm0 = fmaxf(tm0, __shfl_xor_sync(0xffffffffu, tm0, 2));
      tm1 = fmaxf(tm1, __shfl_xor_sync(0xffffffffu, tm1, 1));
      tm1 = fmaxf(tm1, __shfl_xor_sync(0xffffffffu, tm1, 2));
      const float mn0 = fmaxf(m0, tm0), mn1 = fmaxf(m1, tm1);
      const float aa0 = fexp2(m0 - mn0), aa1 = fexp2(m1 - mn1);
      m0 = mn0; m1 = mn1;
      float ts0 = 0.f, ts1 = 0.f;
      unsigned pH[4][4];
      #pragma unroll
      for (int kc = 0; kc < 4; kc++) {
        float e00 = fexp2(s8[2*kc][0]   - m0), e01 = fexp2(s8[2*kc][1]   - m0);
        float e02 = fexp2(s8[2*kc][2]   - m1), e03 = fexp2(s8[2*kc][3]   - m1);
        float e10 = fexp2(s8[2*kc+1][0] - m0), e11 = fexp2(s8[2*kc+1][1] - m0);
        float e12 = fexp2(s8[2*kc+1][2] - m1), e13 = fexp2(s8[2*kc+1][3] - m1);
        ts0 += e00 + e01 + e10 + e11;
        ts1 += e02 + e03 + e12 + e13;
        pH[kc][0] = pack_h2(e00, e01);
        pH[kc][1] = pack_h2(e02, e03);
        pH[kc][2] = pack_h2(e10, e11);
        pH[kc][3] = pack_h2(e12, e13);
      }
      ts0 += __shfl_xor_sync(0xffffffffu, ts0, 1);
      ts0 += __shfl_xor_sync(0xffffffffu, ts0, 2);
      ts1 += __shfl_xor_sync(0xffffffffu, ts1, 1);
      ts1 += __shfl_xor_sync(0xffffffffu, ts1, 2);
      l0 = l0 * aa0 + ts0;
      l1 = l1 * aa1 + ts1;
      #pragma unroll
      for (int nt = 0; nt < 16; nt++) {
        o[nt][0] *= aa0; o[nt][1] *= aa0;
        o[nt][2] *= aa1; o[nt][3] *= aa1;
      }
      #pragma unroll
      for (int kc = 0; kc < 4; kc++) {
        #pragma unroll
        for (int ntp = 0; ntp < 8; ntp++) {
          const unsigned voff = (unsigned)((kc * 16 + ar) * AT_RS + ntp * 32 + aco);
          unsigned vh[4];
          ldsm4t(vh, kvb + AT_TSZ + voff);
          #pragma unroll
          for (int hf = 0; hf < 2; hf++)
            mma16816(o[ntp * 2 + hf], pH[kc], vh[hf*2], vh[hf*2+1]);
        }
      }
    }
    __syncthreads();
  }

  const float inv0 = 1.f / l0, inv1 = 1.f / l1;
  #pragma unroll
  for (int nt = 0; nt < 16; nt++) {
    const int col = h * HD_ + nt * 8 + ((lane & 3) << 1);
    size_t b0 = (size_t)rlo * H_ + col;
    size_t b1 = (size_t)(rlo + 8) * H_ + col;
    *(unsigned*)(out + b0) = pack_h2(o[nt][0] * inv0, o[nt][1] * inv0);
    *(unsigned*)(out + b1) = pack_h2(o[nt][2] * inv1, o[nt][3] * inv1);
  }
}

// ---------------- gating + routing ----------------
__global__ void __launch_bounds__(256) gate_kernel(const float* __restrict__ gw) {
  const int t = blockIdx.x;
  __shared__ float part[256];
  const int tid = threadIdx.x;
  const int e = tid & 15, c = tid >> 4;
  const fp16* xh = g_h3n + (size_t)t*H_;
  float s = 0.f;
  for (int h = c*128; h < c*128+128; h++)
    s += __half2float(xh[h]) * gw[h*E_ + e];
  part[tid] = s;
  __syncthreads();
  if (tid == 0) {
    float lg[16];
    for (int ee=0; ee<16; ee++){ float v=0.f; for (int cc=0; cc<16; cc++) v += part[cc*16+ee]; lg[ee]=v; }
    int i1 = 0;
    for (int ee=1; ee<16; ee++) if (lg[ee] > lg[i1]) i1 = ee;
    int i2 = (i1==0) ? 1 : 0;
    for (int ee=0; ee<16; ee++) if (ee!=i1 && lg[ee] > lg[i2]) i2 = ee;
    float mx = lg[i1];
    float p1 = expf(lg[i1]-mx), p2 = expf(lg[i2]-mx);
    float d = p1 + p2;
    g_topi[t*2]=i1; g_topi[t*2+1]=i2;
    g_topw[t*2]=p1/d; g_topw[t*2+1]=p2/d;
  }
}

__global__ void moe_zero_kernel(){ if (threadIdx.x < E_){ g_cnt[threadIdx.x]=0; g_cur[threadIdx.x]=0; } }
__global__ void moe_count_kernel(){ int i = blockIdx.x*256+threadIdx.x; if (i < P_) atomicAdd(&g_cnt[g_topi[i]], 1); }
__global__ void moe_scan_kernel(){ if (threadIdx.x==0){ int o=0; for (int e=0;e<E_;e++){ g_off[e]=o; o+=g_cnt[e]; } } }
__global__ void moe_scatter_kernel(){
  int i = blockIdx.x*256+threadIdx.x;
  if (i < P_) {
    int e = g_topi[i];
    int pos = g_off[e] + atomicAdd(&g_cur[e], 1);
    g_ptok[pos] = i >> 1;
    g_pslot[i]  = pos;
    g_wslot[pos] = g_topw[i];
  }
}

// ---------------- host ----------------
extern "C" void kernel_launch(void* const* d_in, const int* in_sizes, int n_in,
                              void* d_out, int out_size) {
  (void)in_sizes; (void)n_in; (void)out_size;
  const float* x      = (const float*)d_in[0];
  const float* ln_in  = (const float*)d_in[1];
  const float* ln_post= (const float*)d_in[2];
  const float* ln_res = (const float*)d_in[3];
  const float* wqkv   = (const float*)d_in[4];
  const float* wo     = (const float*)d_in[5];
  const float* w13    = (const float*)d_in[6];
  const float* w2     = (const float*)d_in[7];
  const float* gw     = (const float*)d_in[8];
  const float* ws     = (const float*)d_in[9];
  const float* w2s    = (const float*)d_in[10];
  float* out = (float*)d_out;

  float *resat;
  cudaGetSymbolAddress((void**)&resat,g_resat);

  fp16 *qkvh,*xn,*attn,*h2n,*hmid,*h3n,*hmm,*ymh;
  cudaGetSymbolAddress((void**)&qkvh, g_qkvh);
  cudaGetSymbolAddress((void**)&xn,   g_xn);
  cudaGetSymbolAddress((void**)&attn, g_attn);
  cudaGetSymbolAddress((void**)&h2n,  g_h2n);
  cudaGetSymbolAddress((void**)&hmid, g_hmid);
  cudaGetSymbolAddress((void**)&h3n,  g_h3n);
  cudaGetSymbolAddress((void**)&hmm,  g_hmm);
  cudaGetSymbolAddress((void**)&ymh,  g_ymh);

  fp16 *wq,*wo16,*w1316,*w216,*ws16,*w2s16;
  cudaGetSymbolAddress((void**)&wq,    g_wqkvT);
  cudaGetSymbolAddress((void**)&wo16,  g_woT);
  cudaGetSymbolAddress((void**)&w1316, g_w13T);
  cudaGetSymbolAddress((void**)&w216,  g_w2T);
  cudaGetSymbolAddress((void**)&ws16,  g_ws);
  cudaGetSymbolAddress((void**)&w2s16, g_w2s);

  cudaFuncSetAttribute(mma_gemm, cudaFuncAttributeMaxDynamicSharedMemorySize, MMA_SMEM);
  cudaFuncSetAttribute(attn_mma, cudaFuncAttributeMaxDynamicSharedMemorySize, AT_SMEM);

  // fork a side stream (host objects only; created once per host invocation).
  cudaStream_t s1;
  cudaStreamCreateWithFlags(&s1, cudaStreamNonBlocking);
  cudaEvent_t evFork, evWq, evW, evXN, evJoin;
  cudaEventCreateWithFlags(&evFork, cudaEventDisableTiming);
  cudaEventCreateWithFlags(&evWq,   cudaEventDisableTiming);
  cudaEventCreateWithFlags(&evW,    cudaEventDisableTiming);
  cudaEventCreateWithFlags(&evXN,   cudaEventDisableTiming);
  cudaEventCreateWithFlags(&evJoin, cudaEventDisableTiming);

  cudaEventRecord(evFork, 0);
  cudaStreamWaitEvent(s1, evFork, 0);

  // ---- main stream start: shared-reduction dual rmsnorm (xn for attn, h3n for MoE) ----
  rmsnorm_dual<<<T_, 256>>>(x, ln_in, ln_post, xn, h3n);
  cudaEventRecord(evXN, 0);

  // ---- side stream: wqkv transpose first (main waits on it), then the rest ----
  transpose_h<<<dim3(QKVW_/32, H_/32), 256, 0, s1>>>(wqkv, wq, H_, QKVW_, 0);
  cudaEventRecord(evWq, s1);
  transpose_h<<<dim3(H_/32,   H_/32), 256, 0, s1>>>(wo,  wo16,  H_, H_, 0);
  transpose_h<<<dim3(2*H_/32, H_/32), 256, 0, s1>>>(w13, w1316, H_, 2*H_, 1);
  transpose_h<<<dim3(H_/32,   H_/32), 256, 0, s1>>>(w2,  w216,  H_, H_, 0);
  cudaEventRecord(evW, s1);
  convert_ws_int<<<(E_*2*I_*H_)/2048, 256, 0, s1>>>(ws, ws16);
  convert_h8<<<(E_*H_*I_)/2048, 256, 0, s1>>>(w2s, w2s16);
  cudaStreamWaitEvent(s1, evXN, 0);
  gate_kernel<<<T_, 256, 0, s1>>>(gw);
  moe_zero_kernel<<<1, 32, 0, s1>>>();
  moe_count_kernel<<<P_/256, 256, 0, s1>>>();
  moe_scan_kernel<<<1, 32, 0, s1>>>();
  moe_scatter_kernel<<<P_/256, 256, 0, s1>>>();
  mma_gemm<<<dim3(2*I_/128, T_/128, E_), 256, MMA_SMEM, s1>>>(h3n, ws16, nullptr, hmm, nullptr, 2*I_, H_, 1, 1);
  mma_gemm<<<dim3(H_/128, T_/128, E_), 256, MMA_SMEM, s1>>>(hmm, w2s16, nullptr, ymh, nullptr, H_, I_, 2, 4);
  cudaEventRecord(evJoin, s1);

  // ---- main stream: attention chain + residual MLP (+ fused final) ----
  cudaStreamWaitEvent(0, evWq, 0);
  mma_gemm<<<dim3(QKVW_/128, T_/128, 1), 256, MMA_SMEM>>>(xn, wq, nullptr, qkvh, nullptr, QKVW_, H_, 0, 3);
  rope_split_kernel<<<dim3(T_, NH_ + 2*NKV_), 64>>>(qkvh);
  attn_mma<<<dim3(NH_, T_/128), 256, AT_SMEM>>>(attn);
  cudaStreamWaitEvent(0, evW, 0);
  mma_gemm<<<dim3(H_/128, T_/128, 1), 256, MMA_SMEM>>>(attn, wo16, resat, nullptr, x, H_, H_, 0, 2);
  rmsnorm_h<<<T_, 256>>>(resat, ln_res, h2n);
  mma_gemm<<<dim3(2*H_/128, T_/128, 1), 256, MMA_SMEM>>>(h2n, w1316, nullptr, hmid, nullptr, 2*H_, H_, 0, 1);
  cudaStreamWaitEvent(0, evJoin, 0);
  mma_gemm<<<dim3(H_/128, T_/128, 1), 256, MMA_SMEM>>>(hmid, w216, out, nullptr, resat, H_, H_, 0, 5);
}

// round 17
// speedup vs baseline: 1.0187x; 1.0153x over previous
#include <cuda_runtime.h>
#include <cuda_fp16.h>
#include <math.h>

#define T_ 2048
#define H_ 2048
#define NH_ 16
#define NKV_ 4
#define HD_ 128
#define I_ 1024
#define E_ 16
#define TOPK_ 2
#define P_ (T_*TOPK_)
#define QKVW_ 3072

typedef __half fp16;

// ---------------- scratch (device globals; no allocations allowed) ----------------
__device__ float g_resat[T_*H_];
__device__ float g_mlp[T_*H_];

__device__ fp16 g_qkvh[T_*QKVW_];
__device__ fp16 g_xn[T_*H_];
__device__ fp16 g_attn[T_*H_];
__device__ fp16 g_h2n[T_*H_];
__device__ fp16 g_hmid[T_*H_];
__device__ fp16 g_h3n[T_*H_];
__device__ fp16 g_hmm[P_*I_];
__device__ fp16 g_ymh[P_*H_];

__device__ fp16 g_q[NH_*T_*HD_];
__device__ fp16 g_k[NKV_*T_*HD_];
__device__ fp16 g_v[NKV_*T_*HD_];

__device__ fp16 g_wqkvT[QKVW_*H_];
__device__ fp16 g_woT[H_*H_];
__device__ fp16 g_w13T[2*H_*H_];     // gate/up interleaved rows
__device__ fp16 g_w2T[H_*H_];
__device__ fp16 g_ws[E_*2*I_*H_];    // gate/up interleaved rows per expert
__device__ fp16 g_w2s[E_*H_*I_];

__device__ int   g_topi[P_];
__device__ float g_topw[P_];
__device__ float g_wslot[P_];
__device__ int   g_cnt[E_];
__device__ int   g_off[E_];
__device__ int   g_cur[E_];
__device__ int   g_ptok[P_];
__device__ int   g_pslot[P_];

// ---------------- ptx helpers (base compute_103-safe) ----------------
__device__ __forceinline__ unsigned smem_u32(const void* p) {
  unsigned a;
  asm("{ .reg .u64 t; cvta.to.shared.u64 t, %1; cvt.u32.u64 %0, t; }" : "=r"(a) : "l"(p));
  return a;
}
__device__ __forceinline__ void cp16(unsigned dst, const void* src, bool valid) {
  int sz = valid ? 16 : 0;
  asm volatile("cp.async.cg.shared.global [%0], [%1], 16, %2;"
               :: "r"(dst), "l"(src), "r"(sz) : "memory");
}
#define CP_COMMIT() asm volatile("cp.async.commit_group;" ::: "memory")
#define CP_WAIT(n)  asm volatile("cp.async.wait_group %0;" :: "n"(n) : "memory")

__device__ __forceinline__ void ldsm4(unsigned* r, unsigned addr) {
  asm volatile("ldmatrix.sync.aligned.m8n8.x4.shared.b16 {%0,%1,%2,%3}, [%4];"
               : "=r"(r[0]), "=r"(r[1]), "=r"(r[2]), "=r"(r[3]) : "r"(addr));
}
__device__ __forceinline__ void ldsm4t(unsigned* r, unsigned addr) {
  asm volatile("ldmatrix.sync.aligned.m8n8.x4.trans.shared.b16 {%0,%1,%2,%3}, [%4];"
               : "=r"(r[0]), "=r"(r[1]), "=r"(r[2]), "=r"(r[3]) : "r"(addr));
}
__device__ __forceinline__ void mma16816(float* d, const unsigned* a, unsigned b0, unsigned b1) {
  asm volatile("mma.sync.aligned.m16n8k16.row.col.f32.f16.f16.f32 "
               "{%0,%1,%2,%3}, {%4,%5,%6,%7}, {%8,%9}, {%0,%1,%2,%3};"
               : "+f"(d[0]), "+f"(d[1]), "+f"(d[2]), "+f"(d[3])
               : "r"(a[0]), "r"(a[1]), "r"(a[2]), "r"(a[3]), "r"(b0), "r"(b1));
}

// fast 2^y on the FMA pipe (y in [-1e30, 0]); rel err < 3e-6
__device__ __forceinline__ float fexp2(float y) {
  y = fmaxf(y, -120.f);
  float z = y + 12582912.0f;
  int   n = __float_as_int(z) - 0x4B400000;
  float f = y - (z - 12582912.0f);
  float p = 0.0013333558f;
  p = fmaf(p, f, 0.0096181291f);
  p = fmaf(p, f, 0.0555041087f);
  p = fmaf(p, f, 0.2402265069f);
  p = fmaf(p, f, 0.6931471806f);
  p = fmaf(p, f, 1.0f);
  return p * __int_as_float((n + 127) << 23);
}

__device__ __forceinline__ unsigned pack_h2(float a, float b) {
  __half2 t = __floats2half2_rn(a, b);
  return *(unsigned*)&t;
}
__device__ __forceinline__ void store_h4(float4 v, fp16* p) {
  fp16 h[4] = {__float2half_rn(v.x), __float2half_rn(v.y), __float2half_rn(v.z), __float2half_rn(v.w)};
  *(uint2*)p = *(uint2*)h;
}
__device__ __forceinline__ float siluf(float g){ return g / (1.f + __expf(-g)); }

// ---------------- weight prep ----------------
__global__ void __launch_bounds__(256) convert_ws_int(const float* __restrict__ in, fp16* __restrict__ o) {
  size_t idx = (size_t)blockIdx.x * 256 + threadIdx.x;
  size_t r = idx >> 8;
  int h0 = (int)(idx & 255) << 3;
  int e = (int)(r >> 11);
  int k = (int)(r & 2047);
  int srcr = e * 2 * I_ + ((k & 1) ? I_ + (k >> 1) : (k >> 1));
  const float4* s = (const float4*)(in + (size_t)srcr * H_ + h0);
  float4 a = s[0], b = s[1];
  fp16 hb[8] = {__float2half_rn(a.x), __float2half_rn(a.y), __float2half_rn(a.z), __float2half_rn(a.w),
                __float2half_rn(b.x), __float2half_rn(b.y), __float2half_rn(b.z), __float2half_rn(b.w)};
  *(uint4*)(o + r * H_ + h0) = *(uint4*)hb;
}

__global__ void __launch_bounds__(256) convert_h8(const float* __restrict__ in, fp16* __restrict__ o) {
  size_t i = ((size_t)blockIdx.x * 256 + threadIdx.x) << 3;
  const float4* s = (const float4*)(in + i);
  float4 a = s[0], b = s[1];
  fp16 hb[8] = {__float2half_rn(a.x), __float2half_rn(a.y), __float2half_rn(a.z), __float2half_rn(a.w),
                __float2half_rn(b.x), __float2half_rn(b.y), __float2half_rn(b.z), __float2half_rn(b.w)};
  *(uint4*)(o + i) = *(uint4*)hb;
}

// transpose: in[K][N] fp32 -> o [N][K] fp16; il=1 interleaves gate/up dest rows.
__global__ void __launch_bounds__(256) transpose_h(const float* __restrict__ in, fp16* __restrict__ o,
                                                   int K, int N, int il) {
  __shared__ float t[32][33];
  int k0 = blockIdx.y * 32, n0 = blockIdx.x * 32;
  int tx = threadIdx.x & 31, ty = threadIdx.x >> 5;
  #pragma unroll
  for (int j = 0; j < 4; j++)
    t[ty + 8 * j][tx] = in[(size_t)(k0 + ty + 8 * j) * N + n0 + tx];
  __syncthreads();
  int half = N >> 1;
  #pragma unroll
  for (int j = 0; j < 4; j++) {
    int n = n0 + ty + 8 * j;
    int dr = il ? ((n < half) ? 2 * n : 2 * (n - half) + 1) : n;
    o[(size_t)dr * K + k0 + tx] = __float2half_rn(t[tx][ty + 8 * j]);
  }
}

// ---------------- RMSNorm (single + dual output) ----------------
__global__ void __launch_bounds__(256) rmsnorm_h(const float* __restrict__ x,
                                                 const float* __restrict__ w,
                                                 fp16* __restrict__ o) {
  const int t = blockIdx.x;
  const float4* xr = (const float4*)(x + (size_t)t * H_);
  const float4* wr = (const float4*)w;
  const int i0 = threadIdx.x, i1 = threadIdx.x + 256;
  float4 v0 = xr[i0], v1 = xr[i1];
  float s = v0.x*v0.x+v0.y*v0.y+v0.z*v0.z+v0.w*v0.w
          + v1.x*v1.x+v1.y*v1.y+v1.z*v1.z+v1.w*v1.w;
  #pragma unroll
  for (int off = 16; off; off >>= 1) s += __shfl_xor_sync(0xffffffffu, s, off);
  __shared__ float red[8];
  __shared__ float sinv;
  if ((threadIdx.x & 31) == 0) red[threadIdx.x >> 5] = s;
  __syncthreads();
  if (threadIdx.x == 0) {
    float tt = 0.f;
    #pragma unroll
    for (int k = 0; k < 8; k++) tt += red[k];
    sinv = rsqrtf(tt * (1.f / H_) + 1e-5f);
  }
  __syncthreads();
  float r = sinv;
  float4 w0 = wr[i0], w1 = wr[i1];
  float4 o0, o1;
  o0.x=v0.x*r*w0.x; o0.y=v0.y*r*w0.y; o0.z=v0.z*r*w0.z; o0.w=v0.w*r*w0.w;
  o1.x=v1.x*r*w1.x; o1.y=v1.y*r*w1.y; o1.z=v1.z*r*w1.z; o1.w=v1.w*r*w1.w;
  size_t base = (size_t)t * H_;
  store_h4(o0, o + base + i0 * 4);
  store_h4(o1, o + base + i1 * 4);
}

// shared 1/rms reduction, two weight vectors, two outputs (ln_in / ln_post of same x)
__global__ void __launch_bounds__(256) rmsnorm_dual(const float* __restrict__ x,
                                                    const float* __restrict__ wa,
                                                    const float* __restrict__ wb,
                                                    fp16* __restrict__ oa,
                                                    fp16* __restrict__ ob) {
  const int t = blockIdx.x;
  const float4* xr = (const float4*)(x + (size_t)t * H_);
  const int i0 = threadIdx.x, i1 = threadIdx.x + 256;
  float4 v0 = xr[i0], v1 = xr[i1];
  float s = v0.x*v0.x+v0.y*v0.y+v0.z*v0.z+v0.w*v0.w
          + v1.x*v1.x+v1.y*v1.y+v1.z*v1.z+v1.w*v1.w;
  #pragma unroll
  for (int off = 16; off; off >>= 1) s += __shfl_xor_sync(0xffffffffu, s, off);
  __shared__ float red[8];
  __shared__ float sinv;
  if ((threadIdx.x & 31) == 0) red[threadIdx.x >> 5] = s;
  __syncthreads();
  if (threadIdx.x == 0) {
    float tt = 0.f;
    #pragma unroll
    for (int k = 0; k < 8; k++) tt += red[k];
    sinv = rsqrtf(tt * (1.f / H_) + 1e-5f);
  }
  __syncthreads();
  float r = sinv;
  size_t base = (size_t)t * H_;
  {
    float4 wA0 = ((const float4*)wa)[i0], wA1 = ((const float4*)wa)[i1];
    float4 a0 = make_float4(v0.x*r*wA0.x, v0.y*r*wA0.y, v0.z*r*wA0.z, v0.w*r*wA0.w);
    float4 a1 = make_float4(v1.x*r*wA1.x, v1.y*r*wA1.y, v1.z*r*wA1.z, v1.w*r*wA1.w);
    store_h4(a0, oa + base + i0 * 4);
    store_h4(a1, oa + base + i1 * 4);
  }
  {
    float4 wB0 = ((const float4*)wb)[i0], wB1 = ((const float4*)wb)[i1];
    float4 b0 = make_float4(v0.x*r*wB0.x, v0.y*r*wB0.y, v0.z*r*wB0.z, v0.w*r*wB0.w);
    float4 b1 = make_float4(v1.x*r*wB1.x, v1.y*r*wB1.y, v1.z*r*wB1.z, v1.w*r*wB1.w);
    store_h4(b0, ob + base + i0 * 4);
    store_h4(b1, ob + base + i1 * 4);
  }
}

// ---------------- mma.sync fp16 GEMM with fused epilogues ----------------
// CTA tile 128x128, 8 warps (2m x 4n), warp tile 64x32, K-chunk 64, 3-stage cp.async,
// 2 CTAs/SM, ONE barrier per chunk (3-stage makes the trailing barrier redundant).
// modes:
// 0: fp32 to C.  1: gate/up interleaved -> silu(g)*u fp16 to Ch (Nout=N/2).
// 2: C = Xres + acc (fp32, dense).  3: fp16 to Ch.
// 4: fp16 to Ch scaled by g_wslot[row] (grouped=2 MoE down-proj).
#define MMA_STG 36864
#define MMA_SMEM (3*MMA_STG + 512)
__global__ void __launch_bounds__(256, 2) mma_gemm(const fp16* __restrict__ A,
                                                   const fp16* __restrict__ B,
                                                   float* __restrict__ C,
                                                   fp16* __restrict__ Ch,
                                                   const float* __restrict__ Xres,
                                                   int N, int K, int grouped, int mode) {
  extern __shared__ char smem[];
  const int tid = threadIdx.x, wid = tid >> 5, lane = tid & 31;
  const int e = blockIdx.z;
  int count = 0, sbase = 0;
  if (grouped) {
    count = g_cnt[e];
    if ((int)(blockIdx.y << 7) >= count) return;
    sbase = g_off[e];
  }
  const fp16* BE = B + (size_t)e * N * K;
  const int m0 = blockIdx.y << 7, n0 = blockIdx.x << 7;
  unsigned sb = smem_u32(smem);
  int* rowmap = (int*)(smem + 3*MMA_STG);

  if (tid < 128) {
    int gr = m0 + tid;
    if (grouped) {
      if (m0 + tid < count) {
        int slot = sbase + m0 + tid;
        gr = (grouped == 1) ? g_ptok[slot] : slot;
      } else gr = -1;
    }
    rowmap[tid] = gr;
  }
  __syncthreads();

  const int nk = K >> 6;
  auto load_chunk = [&](int c, int st) {
    unsigned base = sb + (unsigned)st * MMA_STG;
    #pragma unroll
    for (int i = 0; i < 8; i++) {              // A+B: 2048 cp16
      int s = tid + (i << 8);
      int mat = s >> 10, r = (s >> 3) & 127, cq = s & 7;
      unsigned dst = base + (unsigned)mat * 18432u + (unsigned)(r * 144 + cq * 16);
      const fp16* src;
      bool valid = true;
      if (mat == 0) {
        int gr = rowmap[r];
        valid = (gr >= 0);
        if (!valid) gr = 0;
        src = A + (size_t)gr * K + (c << 6) + (cq << 3);
      } else {
        src = BE + (size_t)(n0 + r) * K + (c << 6) + (cq << 3);
      }
      cp16(dst, src, valid);
    }
    CP_COMMIT();
  };

  float acc[4][4][4];
  #pragma unroll
  for (int i = 0; i < 4; i++)
    #pragma unroll
    for (int j = 0; j < 4; j++)
      #pragma unroll
      for (int k = 0; k < 4; k++) acc[i][j][k] = 0.f;

  const int wm = (wid >> 2) << 6;           // 0 or 64
  const int wn = (wid & 3) << 5;            // 0,32,64,96
  const int ar  = lane & 15;
  const unsigned aco = (lane & 16) ? 16u : 0u;
  const int bn  = (lane & 7) + ((lane & 16) ? 8 : 0);
  const unsigned bko = (lane & 8) ? 16u : 0u;

  load_chunk(0, 0);
  if (nk > 1) load_chunk(1, 1);
  int st = 0;
  for (int c = 0; c < nk; c++) {
    if (c + 1 < nk) CP_WAIT(1); else CP_WAIT(0);
    __syncthreads();
    if (c + 2 < nk) {
      int st2 = st + 2; if (st2 >= 3) st2 -= 3;
      load_chunk(c + 2, st2);
    }
    const unsigned stb = sb + (unsigned)st * MMA_STG;
    #pragma unroll
    for (int ks = 0; ks < 4; ks++) {
      const unsigned kb = (unsigned)(ks << 5);
      unsigned ahf[4][4];
      #pragma unroll
      for (int mi = 0; mi < 4; mi++) {
        unsigned rowA = (unsigned)((wm + mi * 16 + ar) * 144);
        ldsm4(ahf[mi], stb + rowA + kb + aco);
      }
      #pragma unroll
      for (int nb = 0; nb < 2; nb++) {
        unsigned rowB = (unsigned)((wn + nb * 16 + bn) * 144);
        unsigned bhf[4];
        ldsm4(bhf, stb + 18432u + rowB + kb + bko);
        #pragma unroll
        for (int mi = 0; mi < 4; mi++) {
          #pragma unroll
          for (int half = 0; half < 2; half++) {
            mma16816(acc[mi][nb * 2 + half], ahf[mi], bhf[half * 2], bhf[half * 2 + 1]);
          }
        }
      }
    }
    // no trailing barrier: with 3 stages, the next write into this buffer (chunk
    // c+3) is issued in iteration c+1 strictly after its top __syncthreads().
    if (++st == 3) st = 0;
  }

  #pragma unroll
  for (int mi = 0; mi < 4; mi++) {
    const int lr0 = wm + mi * 16 + (lane >> 2);
    const int gr0 = m0 + lr0;
    const bool st0 = !grouped || (gr0 < count);
    const bool st1 = !grouped || (gr0 + 8 < count);
    const size_t row0 = (size_t)((grouped ? sbase : 0) + gr0);
    if (mode == 1) {
      const int Nout = N >> 1;
      #pragma unroll
      for (int nt = 0; nt < 4; nt++) {
        const int col = n0 + wn + nt * 8 + ((lane & 3) << 1);
        const int j = col >> 1;
        float* d = acc[mi][nt];
        if (st0) Ch[row0 * Nout + j]       = __float2half_rn(siluf(d[0]) * d[1]);
        if (st1) Ch[(row0 + 8) * Nout + j] = __float2half_rn(siluf(d[2]) * d[3]);
      }
    } else if (mode == 2) {
      #pragma unroll
      for (int nt = 0; nt < 4; nt++) {
        const int col = n0 + wn + nt * 8 + ((lane & 3) << 1);
        float* d = acc[mi][nt];
        float2 r0 = *(const float2*)(Xres + row0 * N + col);
        float2 r1 = *(const float2*)(Xres + (row0 + 8) * N + col);
        *(float2*)(C + row0 * N + col)       = make_float2(r0.x + d[0], r0.y + d[1]);
        *(float2*)(C + (row0 + 8) * N + col) = make_float2(r1.x + d[2], r1.y + d[3]);
      }
    } else if (mode == 3) {
      #pragma unroll
      for (int nt = 0; nt < 4; nt++) {
        const int col = n0 + wn + nt * 8 + ((lane & 3) << 1);
        float* d = acc[mi][nt];
        if (st0) *(unsigned*)(Ch + row0 * N + col)       = pack_h2(d[0], d[1]);
        if (st1) *(unsigned*)(Ch + (row0 + 8) * N + col) = pack_h2(d[2], d[3]);
      }
    } else if (mode == 4) {
      const float w0s = st0 ? g_wslot[row0]     : 0.f;
      const float w1s = st1 ? g_wslot[row0 + 8] : 0.f;
      #pragma unroll
      for (int nt = 0; nt < 4; nt++) {
        const int col = n0 + wn + nt * 8 + ((lane & 3) << 1);
        float* d = acc[mi][nt];
        if (st0) *(unsigned*)(Ch + row0 * N + col)       = pack_h2(d[0] * w0s, d[1] * w0s);
        if (st1) *(unsigned*)(Ch + (row0 + 8) * N + col) = pack_h2(d[2] * w1s, d[3] * w1s);
      }
    } else {
      #pragma unroll
      for (int nt = 0; nt < 4; nt++) {
        const int col = n0 + wn + nt * 8 + ((lane & 3) << 1);
        float* d = acc[mi][nt];
        if (st0) *(float2*)(C + row0 * N + col)       = make_float2(d[0], d[1]);
        if (st1) *(float2*)(C + (row0 + 8) * N + col) = make_float2(d[2], d[3]);
      }
    }
  }
}

// ---------------- RoPE + pack into per-head fp16 layouts (fp16 input) ----------------
__global__ void rope_split_kernel(const fp16* __restrict__ qkv) {
  const int t = blockIdx.x, hh = blockIdx.y, i = threadIdx.x;
  if (hh < NH_ + NKV_) {
    const fp16* b;
    fp16* d;
    if (hh < NH_) {
      b = qkv + (size_t)t*QKVW_ + hh*HD_;
      d = g_q + ((size_t)hh*T_ + t) * HD_;
    } else {
      int k = hh - NH_;
      b = qkv + (size_t)t*QKVW_ + NH_*HD_ + k*HD_;
      d = g_k + ((size_t)k*T_ + t) * HD_;
    }
    float fr = powf(10000.f, -(float)(2*i) * (1.f/HD_));
    float ang = (float)t * fr;
    float sn, cs; sincosf(ang, &sn, &cs);
    float x1 = __half2float(b[i]), x2 = __half2float(b[i+64]);
    d[i]      = __float2half_rn(x1*cs - x2*sn);
    d[i + 64] = __float2half_rn(x2*cs + x1*sn);
  } else {
    int v = hh - NH_ - NKV_;
    const fp16* b = qkv + (size_t)t*QKVW_ + (NH_+NKV_)*HD_ + v*HD_;
    size_t o = ((size_t)v*T_ + t) * HD_;
    g_v[o + i]      = b[i];
    g_v[o + i + 64] = b[i+64];
  }
}

// ---------------- mma.sync flash attention (single fp16) ----------------
#define AT_RS  272
#define AT_QSZ (128*AT_RS)
#define AT_TSZ (64*AT_RS)
#define AT_SMEM (AT_QSZ + 2*2*AT_TSZ)   // 104448
__global__ void __launch_bounds__(256) attn_mma(fp16* __restrict__ out) {
  extern __shared__ char smc[];
  const int h = blockIdx.x;
  const int q0 = ((int)gridDim.y - 1 - (int)blockIdx.y) << 7;   // heavy tiles first
  const int kvh = h >> 2;
  const int tid = threadIdx.x, wid = tid >> 5, lane = tid & 31;
  const unsigned sb = smem_u32(smc);
  const unsigned KV_o = AT_QSZ;

  #pragma unroll
  for (int i = 0; i < 8; i++) {
    int s = tid + (i << 8);
    int r = (s >> 4) & 127, cq = s & 15;
    unsigned dst = sb + (unsigned)(r * AT_RS + cq * 16);
    const fp16* src = g_q + (((size_t)h*T_ + q0 + r) << 7) + cq*8;
    cp16(dst, src, true);
  }
  CP_COMMIT();

  auto load_kv = [&](int c, int st) {
    unsigned base = sb + KV_o + (unsigned)st * (2*AT_TSZ);
    #pragma unroll
    for (int i = 0; i < 8; i++) {
      int s = tid + (i << 8);
      int mat = s >> 10, r = (s >> 4) & 63, cq = s & 15;
      unsigned dst = base + (unsigned)mat * AT_TSZ + (unsigned)(r * AT_RS + cq * 16);
      const fp16* ap = (mat == 0) ? g_k : g_v;
      cp16(dst, ap + (((size_t)kvh*T_ + c*64 + r) << 7) + cq*8, true);
    }
    CP_COMMIT();
  };

  const int wr0 = wid << 4;
  const int rlo = q0 + wr0 + (lane >> 2);
  float m0 = -1e30f, m1 = -1e30f, l0 = 0.f, l1 = 0.f;
  float o[16][4];
  #pragma unroll
  for (int i = 0; i < 16; i++)
    #pragma unroll
    for (int j = 0; j < 4; j++) o[i][j] = 0.f;

  const int ntl = (q0 >> 6) + 2;
  load_kv(0, 0);

  const int ar  = lane & 15;
  const int aco = (lane >> 4) << 4;
  const int bnr = (lane & 7) + ((lane & 16) ? 8 : 0);
  const int bko = (lane & 8) ? 16 : 0;
  const float sc = 0.12751744f;                    // (1/sqrt(128)) * log2(e)

  for (int c = 0; c < ntl; c++) {
    const int st = c & 1;
    if (c + 1 < ntl) { load_kv(c + 1, st ^ 1); CP_WAIT(1); }
    else CP_WAIT(0);
    __syncthreads();
    const int s0 = c << 6;
    const bool active = (s0 <= q0 + wr0 + 15);
    if (active) {
      const unsigned kvb = sb + KV_o + (unsigned)st * (2*AT_TSZ);
      float s8[8][4];
      #pragma unroll
      for (int i = 0; i < 8; i++)
        #pragma unroll
        for (int j = 0; j < 4; j++) s8[i][j] = 0.f;
      #pragma unroll
      for (int kk = 0; kk < 8; kk++) {
        const unsigned qoff = (unsigned)((wr0 + ar) * AT_RS + kk * 32 + aco);
        unsigned ah[4];
        ldsm4(ah, sb + qoff);
        #pragma unroll
        for (int ntp = 0; ntp < 4; ntp++) {
          const unsigned koff = (unsigned)((bnr + ntp * 16) * AT_RS + kk * 32 + bko);
          unsigned bh[4];
          ldsm4(bh, kvb + koff);
          #pragma unroll
          for (int hf = 0; hf < 2; hf++)
            mma16816(s8[ntp * 2 + hf], ah, bh[hf*2], bh[hf*2+1]);
        }
      }
      #pragma unroll
      for (int nt = 0; nt < 8; nt++)
        #pragma unroll
        for (int j = 0; j < 4; j++) s8[nt][j] *= sc;
      if (s0 + 63 > q0 + wr0) {
        const int cb = s0 + ((lane & 3) << 1);
        #pragma unroll
        for (int nt = 0; nt < 8; nt++) {
          #pragma unroll
          for (int j = 0; j < 2; j++) {
            int col = cb + nt * 8 + j;
            if (col > rlo)     s8[nt][j]     = -1e30f;
            if (col > rlo + 8) s8[nt][j + 2] = -1e30f;
          }
        }
      }
      float tm0 = -1e30f, tm1 = -1e30f;
      #pragma unroll
      for (int nt = 0; nt < 8; nt++) {
        tm0 = fmaxf(tm0, fmaxf(s8[nt][0], s8[nt][1]));
        tm1 = fmaxf(tm1, fmaxf(s8[nt][2], s8[nt][3]));
      }
      tm0 = fmaxf(tm0, __shfl_xor_sync(0xffffffffu, tm0, 1));
      tm0 = fmaxf(tm0, __shfl_xor_sync(0xffffffffu, tm0, 2));
      tm1 = fmaxf(tm1, __shfl_xor_sync(0xffffffffu, tm1, 1));
      tm1 = fmaxf(tm1, __shfl_xor_sync(0xffffffffu, tm1, 2));
      const float mn0 = fmaxf(m0, tm0), mn1 = fmaxf(m1, tm1);
      const float aa0 = fexp2(m0 - mn0), aa1 = fexp2(m1 - mn1);
      m0 = mn0; m1 = mn1;
      float ts0 = 0.f, ts1 = 0.f;
      unsigned pH[4][4];
      #pragma unroll
      for (int kc = 0; kc < 4; kc++) {
        float e00 = fexp2(s8[2*kc][0]   - m0), e01 = fexp2(s8[2*kc][1]   - m0);
        float e02 = fexp2(s8[2*kc][2]   - m1), e03 = fexp2(s8[2*kc][3]   - m1);
        float e10 = fexp2(s8[2*kc+1][0] - m0), e11 = fexp2(s8[2*kc+1][1] - m0);
        float e12 = fexp2(s8[2*kc+1][2] - m1), e13 = fexp2(s8[2*kc+1][3] - m1);
        ts0 += e00 + e01 + e10 + e11;
        ts1 += e02 + e03 + e12 + e13;
        pH[kc][0] = pack_h2(e00, e01);
        pH[kc][1] = pack_h2(e02, e03);
        pH[kc][2] = pack_h2(e10, e11);
        pH[kc][3] = pack_h2(e12, e13);
      }
      ts0 += __shfl_xor_sync(0xffffffffu, ts0, 1);
      ts0 += __shfl_xor_sync(0xffffffffu, ts0, 2);
      ts1 += __shfl_xor_sync(0xffffffffu, ts1, 1);
      ts1 += __shfl_xor_sync(0xffffffffu, ts1, 2);
      l0 = l0 * aa0 + ts0;
      l1 = l1 * aa1 + ts1;
      #pragma unroll
      for (int nt = 0; nt < 16; nt++) {
        o[nt][0] *= aa0; o[nt][1] *= aa0;
        o[nt][2] *= aa1; o[nt][3] *= aa1;
      }
      #pragma unroll
      for (int kc = 0; kc < 4; kc++) {
        #pragma unroll
        for (int ntp = 0; ntp < 8; ntp++) {
          const unsigned voff = (unsigned)((kc * 16 + ar) * AT_RS + ntp * 32 + aco);
          unsigned vh[4];
          ldsm4t(vh, kvb + AT_TSZ + voff);
          #pragma unroll
          for (int hf = 0; hf < 2; hf++)
            mma16816(o[ntp * 2 + hf], pH[kc], vh[hf*2], vh[hf*2+1]);
        }
      }
    }
    __syncthreads();
  }

  const float inv0 = 1.f / l0, inv1 = 1.f / l1;
  #pragma unroll
  for (int nt = 0; nt < 16; nt++) {
    const int col = h * HD_ + nt * 8 + ((lane & 3) << 1);
    size_t b0 = (size_t)rlo * H_ + col;
    size_t b1 = (size_t)(rlo + 8) * H_ + col;
    *(unsigned*)(out + b0) = pack_h2(o[nt][0] * inv0, o[nt][1] * inv0);
    *(unsigned*)(out + b1) = pack_h2(o[nt][2] * inv1, o[nt][3] * inv1);
  }
}

// ---------------- gating + routing ----------------
__global__ void __launch_bounds__(256) gate_kernel(const float* __restrict__ gw) {
  const int t = blockIdx.x;
  __shared__ float part[256];
  const int tid = threadIdx.x;
  const int e = tid & 15, c = tid >> 4;
  const fp16* xh = g_h3n + (size_t)t*H_;
  float s = 0.f;
  for (int h = c*128; h < c*128+128; h++)
    s += __half2float(xh[h]) * gw[h*E_ + e];
  part[tid] = s;
  __syncthreads();
  if (tid == 0) {
    float lg[16];
    for (int ee=0; ee<16; ee++){ float v=0.f; for (int cc=0; cc<16; cc++) v += part[cc*16+ee]; lg[ee]=v; }
    int i1 = 0;
    for (int ee=1; ee<16; ee++) if (lg[ee] > lg[i1]) i1 = ee;
    int i2 = (i1==0) ? 1 : 0;
    for (int ee=0; ee<16; ee++) if (ee!=i1 && lg[ee] > lg[i2]) i2 = ee;
    float mx = lg[i1];
    float p1 = expf(lg[i1]-mx), p2 = expf(lg[i2]-mx);
    float d = p1 + p2;
    g_topi[t*2]=i1; g_topi[t*2+1]=i2;
    g_topw[t*2]=p1/d; g_topw[t*2+1]=p2/d;
  }
}

__global__ void moe_zero_kernel(){ if (threadIdx.x < E_){ g_cnt[threadIdx.x]=0; g_cur[threadIdx.x]=0; } }
__global__ void moe_count_kernel(){ int i = blockIdx.x*256+threadIdx.x; if (i < P_) atomicAdd(&g_cnt[g_topi[i]], 1); }
__global__ void moe_scan_kernel(){ if (threadIdx.x==0){ int o=0; for (int e=0;e<E_;e++){ g_off[e]=o; o+=g_cnt[e]; } } }
__global__ void moe_scatter_kernel(){
  int i = blockIdx.x*256+threadIdx.x;
  if (i < P_) {
    int e = g_topi[i];
    int pos = g_off[e] + atomicAdd(&g_cur[e], 1);
    g_ptok[pos] = i >> 1;
    g_pslot[i]  = pos;
    g_wslot[pos] = g_topw[i];
  }
}

// ---------------- final combine: out = resat + mlp + ymh[p0] + ymh[p1] ----------------
__global__ void final_kernel(float* __restrict__ out) {
  const int t = blockIdx.x;
  const int p0 = g_pslot[t*2], p1 = g_pslot[t*2+1];
  const float4* ra = (const float4*)(g_resat + (size_t)t*H_);
  const float4* ml = (const float4*)(g_mlp   + (size_t)t*H_);
  const __half2* y0 = (const __half2*)(g_ymh + (size_t)p0*H_);
  const __half2* y1 = (const __half2*)(g_ymh + (size_t)p1*H_);
  float4* op = (float4*)(out + (size_t)t*H_);
  for (int i = threadIdx.x; i < 512; i += 256) {
    float4 A = ra[i], B = ml[i];
    float2 c0 = __half22float2(y0[2*i]),   c1 = __half22float2(y0[2*i+1]);
    float2 d0 = __half22float2(y1[2*i]),   d1 = __half22float2(y1[2*i+1]);
    op[i] = make_float4(A.x+B.x+c0.x+d0.x, A.y+B.y+c0.y+d0.y,
                        A.z+B.z+c1.x+d1.x, A.w+B.w+c1.y+d1.y);
  }
}

// ---------------- host ----------------
extern "C" void kernel_launch(void* const* d_in, const int* in_sizes, int n_in,
                              void* d_out, int out_size) {
  (void)in_sizes; (void)n_in; (void)out_size;
  const float* x      = (const float*)d_in[0];
  const float* ln_in  = (const float*)d_in[1];
  const float* ln_post= (const float*)d_in[2];
  const float* ln_res = (const float*)d_in[3];
  const float* wqkv   = (const float*)d_in[4];
  const float* wo     = (const float*)d_in[5];
  const float* w13    = (const float*)d_in[6];
  const float* w2     = (const float*)d_in[7];
  const float* gw     = (const float*)d_in[8];
  const float* ws     = (const float*)d_in[9];
  const float* w2s    = (const float*)d_in[10];
  float* out = (float*)d_out;

  float *resat,*mlp;
  cudaGetSymbolAddress((void**)&resat,g_resat);
  cudaGetSymbolAddress((void**)&mlp,  g_mlp);

  fp16 *qkvh,*xn,*attn,*h2n,*hmid,*h3n,*hmm,*ymh;
  cudaGetSymbolAddress((void**)&qkvh, g_qkvh);
  cudaGetSymbolAddress((void**)&xn,   g_xn);
  cudaGetSymbolAddress((void**)&attn, g_attn);
  cudaGetSymbolAddress((void**)&h2n,  g_h2n);
  cudaGetSymbolAddress((void**)&hmid, g_hmid);
  cudaGetSymbolAddress((void**)&h3n,  g_h3n);
  cudaGetSymbolAddress((void**)&hmm,  g_hmm);
  cudaGetSymbolAddress((void**)&ymh,  g_ymh);

  fp16 *wq,*wo16,*w1316,*w216,*ws16,*w2s16;
  cudaGetSymbolAddress((void**)&wq,    g_wqkvT);
  cudaGetSymbolAddress((void**)&wo16,  g_woT);
  cudaGetSymbolAddress((void**)&w1316, g_w13T);
  cudaGetSymbolAddress((void**)&w216,  g_w2T);
  cudaGetSymbolAddress((void**)&ws16,  g_ws);
  cudaGetSymbolAddress((void**)&w2s16, g_w2s);

  cudaFuncSetAttribute(mma_gemm, cudaFuncAttributeMaxDynamicSharedMemorySize, MMA_SMEM);
  cudaFuncSetAttribute(attn_mma, cudaFuncAttributeMaxDynamicSharedMemorySize, AT_SMEM);

  // fork a side stream (host objects only; created once per host invocation).
  cudaStream_t s1;
  cudaStreamCreateWithFlags(&s1, cudaStreamNonBlocking);
  cudaEvent_t evFork, evWq, evW, evXN, evJoin;
  cudaEventCreateWithFlags(&evFork, cudaEventDisableTiming);
  cudaEventCreateWithFlags(&evWq,   cudaEventDisableTiming);
  cudaEventCreateWithFlags(&evW,    cudaEventDisableTiming);
  cudaEventCreateWithFlags(&evXN,   cudaEventDisableTiming);
  cudaEventCreateWithFlags(&evJoin, cudaEventDisableTiming);

  cudaEventRecord(evFork, 0);
  cudaStreamWaitEvent(s1, evFork, 0);

  // ---- main stream start: shared-reduction dual rmsnorm (xn for attn, h3n for MoE) ----
  rmsnorm_dual<<<T_, 256>>>(x, ln_in, ln_post, xn, h3n);
  cudaEventRecord(evXN, 0);

  // ---- side stream: wqkv transpose first (main waits on it), then the rest ----
  transpose_h<<<dim3(QKVW_/32, H_/32), 256, 0, s1>>>(wqkv, wq, H_, QKVW_, 0);
  cudaEventRecord(evWq, s1);
  transpose_h<<<dim3(H_/32,   H_/32), 256, 0, s1>>>(wo,  wo16,  H_, H_, 0);
  transpose_h<<<dim3(2*H_/32, H_/32), 256, 0, s1>>>(w13, w1316, H_, 2*H_, 1);
  transpose_h<<<dim3(H_/32,   H_/32), 256, 0, s1>>>(w2,  w216,  H_, H_, 0);
  cudaEventRecord(evW, s1);
  convert_ws_int<<<(E_*2*I_*H_)/2048, 256, 0, s1>>>(ws, ws16);
  convert_h8<<<(E_*H_*I_)/2048, 256, 0, s1>>>(w2s, w2s16);
  cudaStreamWaitEvent(s1, evXN, 0);
  gate_kernel<<<T_, 256, 0, s1>>>(gw);
  moe_zero_kernel<<<1, 32, 0, s1>>>();
  moe_count_kernel<<<P_/256, 256, 0, s1>>>();
  moe_scan_kernel<<<1, 32, 0, s1>>>();
  moe_scatter_kernel<<<P_/256, 256, 0, s1>>>();
  mma_gemm<<<dim3(2*I_/128, T_/128, E_), 256, MMA_SMEM, s1>>>(h3n, ws16, nullptr, hmm, nullptr, 2*I_, H_, 1, 1);
  mma_gemm<<<dim3(H_/128, T_/128, E_), 256, MMA_SMEM, s1>>>(hmm, w2s16, nullptr, ymh, nullptr, H_, I_, 2, 4);
  cudaEventRecord(evJoin, s1);

  // ---- main stream: attention chain + residual MLP (W2 overlaps MoE tail) ----
  cudaStreamWaitEvent(0, evWq, 0);
  mma_gemm<<<dim3(QKVW_/128, T_/128, 1), 256, MMA_SMEM>>>(xn, wq, nullptr, qkvh, nullptr, QKVW_, H_, 0, 3);
  rope_split_kernel<<<dim3(T_, NH_ + 2*NKV_), 64>>>(qkvh);
  attn_mma<<<dim3(NH_, T_/128), 256, AT_SMEM>>>(attn);
  cudaStreamWaitEvent(0, evW, 0);
  mma_gemm<<<dim3(H_/128, T_/128, 1), 256, MMA_SMEM>>>(attn, wo16, resat, nullptr, x, H_, H_, 0, 2);
  rmsnorm_h<<<T_, 256>>>(resat, ln_res, h2n);
  mma_gemm<<<dim3(2*H_/128, T_/128, 1), 256, MMA_SMEM>>>(h2n, w1316, nullptr, hmid, nullptr, 2*H_, H_, 0, 1);
  mma_gemm<<<dim3(H_/128, T_/128, 1), 256, MMA_SMEM>>>(hmid, w216, mlp, nullptr, nullptr, H_, H_, 0, 0);

  // ---- join + combine (only the tiny final kernel waits on MoE) ----
  cudaStreamWaitEvent(0, evJoin, 0);
  final_kernel<<<T_, 256>>>(out);
}